// round 1
// baseline (speedup 1.0000x reference)
#include <cuda_runtime.h>

#define WIDTH 1024
#define HEADS 16
#define ACH   64       // attention channels per head
#define BS    2
#define NCTX  1024
#define NDATA 4096

// Scratch buffers (allocation-free rule: __device__ globals)
__device__ float g_q[BS * NCTX * WIDTH];            // 8 MB
__device__ float g_kv[BS * NDATA * 2 * WIDTH];      // 64 MB
__device__ float g_attn[BS * NCTX * WIDTH];         // 8 MB

// ----------------------------------------------------------------------------
// Tiled SGEMM: C[M,N] = A[M,K] @ B[K,N] + bias[N]
// BM=BN=128, BK=8, 256 threads, 8x8 microtile per thread.
// Assumes M%128==0, N%128==0, K%8==0 (true for all three calls).
// ----------------------------------------------------------------------------
__global__ void __launch_bounds__(256) gemm_bias_kernel(
    const float* __restrict__ A, const float* __restrict__ B,
    const float* __restrict__ bias, float* __restrict__ C,
    int M, int N, int K)
{
    __shared__ float As[8][128];   // transposed A tile: As[k][m]
    __shared__ float Bs[8][128];   // Bs[k][n]

    const int tid = threadIdx.x;
    const int tx = tid & 15;       // 0..15  (n direction)
    const int ty = tid >> 4;       // 0..15  (m direction)
    const int bm = blockIdx.y * 128;
    const int bn = blockIdx.x * 128;

    float acc[8][8];
#pragma unroll
    for (int i = 0; i < 8; i++)
#pragma unroll
        for (int j = 0; j < 8; j++) acc[i][j] = 0.0f;

    // A tile load mapping: thread -> (m = tid/2, k4 = (tid%2)*4), one float4
    const int a_m = tid >> 1;
    const int a_k = (tid & 1) * 4;
    // B tile load mapping: thread -> (k = tid/32, n4 = (tid%32)*4), one float4
    const int b_k = tid >> 5;
    const int b_n = (tid & 31) * 4;

    const float* Aptr = A + (bm + a_m) * K + a_k;
    const float* Bptr = B + b_k * N + bn + b_n;

    for (int k0 = 0; k0 < K; k0 += 8) {
        float4 av = *(const float4*)(Aptr + k0);
        float4 bv = *(const float4*)(Bptr + k0 * N);
        As[a_k + 0][a_m] = av.x;
        As[a_k + 1][a_m] = av.y;
        As[a_k + 2][a_m] = av.z;
        As[a_k + 3][a_m] = av.w;
        *(float4*)&Bs[b_k][b_n] = bv;
        __syncthreads();

#pragma unroll
        for (int k = 0; k < 8; k++) {
            float a[8], b[8];
            *(float4*)(a)     = *(const float4*)&As[k][ty * 8];
            *(float4*)(a + 4) = *(const float4*)&As[k][ty * 8 + 4];
            *(float4*)(b)     = *(const float4*)&Bs[k][tx * 8];
            *(float4*)(b + 4) = *(const float4*)&Bs[k][tx * 8 + 4];
#pragma unroll
            for (int i = 0; i < 8; i++)
#pragma unroll
                for (int j = 0; j < 8; j++)
                    acc[i][j] += a[i] * b[j];
        }
        __syncthreads();
    }

    // epilogue with bias
    float bb[8];
#pragma unroll
    for (int j = 0; j < 8; j++) bb[j] = bias[bn + tx * 8 + j];

#pragma unroll
    for (int i = 0; i < 8; i++) {
        int row = bm + ty * 8 + i;
        float4 o0, o1;
        o0.x = acc[i][0] + bb[0]; o0.y = acc[i][1] + bb[1];
        o0.z = acc[i][2] + bb[2]; o0.w = acc[i][3] + bb[3];
        o1.x = acc[i][4] + bb[4]; o1.y = acc[i][5] + bb[5];
        o1.z = acc[i][6] + bb[6]; o1.w = acc[i][7] + bb[7];
        *(float4*)&C[row * N + bn + tx * 8]     = o0;
        *(float4*)&C[row * N + bn + tx * 8 + 4] = o1;
    }
}

// ----------------------------------------------------------------------------
// Flash attention over one (b, h, 64-query tile), looping s in 64 chunks.
// Thread layout: 256 threads = 16(y) x 16(x). Thread owns rows 4y..4y+3 and
// columns 4x..4x+3 of the current 64x64 tile. Online softmax state per row.
//
// smem: Qs [c][r] 16KB (transposed, loaded once)
//       KPs     16KB — K transposed [c][s] during S compute, then P [r][s]
//       Vs [s][c] 16KB
// Total = 48KB exactly (static limit).
// ----------------------------------------------------------------------------
__global__ void __launch_bounds__(256) attn_kernel()
{
    __shared__ float Qs[64][64];    // [c][r]
    __shared__ float KPs[64][64];   // K: [c][s]; later P: [r][s]
    __shared__ float Vs[64][64];    // [s][c]

    const int b  = blockIdx.z;
    const int h  = blockIdx.y;
    const int t0 = blockIdx.x * 64;

    const int tid = threadIdx.x;
    const int x = tid & 15;
    const int y = tid >> 4;

    // Load Q tile, transposed into Qs[c][r]
#pragma unroll
    for (int it = 0; it < 4; it++) {
        int r  = (tid >> 4) + it * 16;
        int c4 = (tid & 15) * 4;
        float4 v = *(const float4*)&g_q[(b * NCTX + t0 + r) * WIDTH + h * ACH + c4];
        Qs[c4 + 0][r] = v.x;
        Qs[c4 + 1][r] = v.y;
        Qs[c4 + 2][r] = v.z;
        Qs[c4 + 3][r] = v.w;
    }

    float m[4], l[4], o[4][4];
#pragma unroll
    for (int i = 0; i < 4; i++) {
        m[i] = -1e30f;
        l[i] = 0.0f;
#pragma unroll
        for (int j = 0; j < 4; j++) o[i][j] = 0.0f;
    }

    for (int s0 = 0; s0 < NDATA; s0 += 64) {
        __syncthreads();   // protects Qs (first iter) and KPs/Vs reuse

        // Load K (transposed -> KPs[c][s]) and V (direct -> Vs[s][c])
#pragma unroll
        for (int it = 0; it < 4; it++) {
            int s  = (tid >> 4) + it * 16;
            int c4 = (tid & 15) * 4;
            const float* kvrow = &g_kv[(b * NDATA + s0 + s) * (2 * WIDTH) + h * 2 * ACH];
            float4 kvk = *(const float4*)(kvrow + c4);
            KPs[c4 + 0][s] = kvk.x;
            KPs[c4 + 1][s] = kvk.y;
            KPs[c4 + 2][s] = kvk.z;
            KPs[c4 + 3][s] = kvk.w;
            float4 vv = *(const float4*)(kvrow + ACH + c4);
            *(float4*)&Vs[s][c4] = vv;
        }
        __syncthreads();

        // S = (Q K^T) * 0.125   (scale = 1/sqrt(sqrt(64)) applied to q and k)
        float sacc[4][4];
#pragma unroll
        for (int i = 0; i < 4; i++)
#pragma unroll
            for (int j = 0; j < 4; j++) sacc[i][j] = 0.0f;

#pragma unroll 16
        for (int c = 0; c < 64; c++) {
            float4 a4 = *(const float4*)&Qs[c][y * 4];
            float4 b4 = *(const float4*)&KPs[c][x * 4];
            float a[4] = {a4.x, a4.y, a4.z, a4.w};
            float bb[4] = {b4.x, b4.y, b4.z, b4.w};
#pragma unroll
            for (int i = 0; i < 4; i++)
#pragma unroll
                for (int j = 0; j < 4; j++)
                    sacc[i][j] += a[i] * bb[j];
        }
#pragma unroll
        for (int i = 0; i < 4; i++)
#pragma unroll
            for (int j = 0; j < 4; j++) sacc[i][j] *= 0.125f;

        // Online softmax update
        float p[4][4];
#pragma unroll
        for (int i = 0; i < 4; i++) {
            float v = fmaxf(fmaxf(sacc[i][0], sacc[i][1]),
                            fmaxf(sacc[i][2], sacc[i][3]));
            v = fmaxf(v, __shfl_xor_sync(0xffffffffu, v, 1));
            v = fmaxf(v, __shfl_xor_sync(0xffffffffu, v, 2));
            v = fmaxf(v, __shfl_xor_sync(0xffffffffu, v, 4));
            v = fmaxf(v, __shfl_xor_sync(0xffffffffu, v, 8));
            float mn = fmaxf(m[i], v);
            float corr = __expf(m[i] - mn);
            m[i] = mn;
            l[i] *= corr;
#pragma unroll
            for (int j = 0; j < 4; j++) {
                p[i][j] = __expf(sacc[i][j] - mn);
                o[i][j] *= corr;
            }
            float rs = p[i][0] + p[i][1] + p[i][2] + p[i][3];
            rs += __shfl_xor_sync(0xffffffffu, rs, 1);
            rs += __shfl_xor_sync(0xffffffffu, rs, 2);
            rs += __shfl_xor_sync(0xffffffffu, rs, 4);
            rs += __shfl_xor_sync(0xffffffffu, rs, 8);
            l[i] += rs;
        }

        __syncthreads();   // all threads done reading K before overwriting with P

        // Write P into KPs as [r][s]
#pragma unroll
        for (int i = 0; i < 4; i++)
#pragma unroll
            for (int j = 0; j < 4; j++)
                KPs[y * 4 + i][x * 4 + j] = p[i][j];
        __syncthreads();

        // O += P @ V  : o[i][j] += sum_s P[4y+i][s] * V[s][4x+j]
#pragma unroll 16
        for (int s = 0; s < 64; s++) {
            float4 b4 = *(const float4*)&Vs[s][x * 4];
            float bb[4] = {b4.x, b4.y, b4.z, b4.w};
            float pa[4];
#pragma unroll
            for (int i = 0; i < 4; i++) pa[i] = KPs[y * 4 + i][s];
#pragma unroll
            for (int i = 0; i < 4; i++)
#pragma unroll
                for (int j = 0; j < 4; j++)
                    o[i][j] += pa[i] * bb[j];
        }
    }

    // Epilogue: normalize and store
#pragma unroll
    for (int i = 0; i < 4; i++) {
        float inv = 1.0f / l[i];
        int t = t0 + y * 4 + i;
#pragma unroll
        for (int j = 0; j < 4; j++) {
            g_attn[(b * NCTX + t) * WIDTH + h * ACH + x * 4 + j] = o[i][j] * inv;
        }
    }
}

// ----------------------------------------------------------------------------
// Launch: q = x@Wq + bq ; kv = data@Wkv + bkv ; attn ; out = attn@Wproj + bproj
// ----------------------------------------------------------------------------
extern "C" void kernel_launch(void* const* d_in, const int* in_sizes, int n_in,
                              void* d_out, int out_size)
{
    (void)in_sizes; (void)n_in; (void)out_size;

    const float* x     = (const float*)d_in[0];
    const float* data  = (const float*)d_in[1];
    const float* Wq    = (const float*)d_in[2];
    const float* bq    = (const float*)d_in[3];
    const float* Wkv   = (const float*)d_in[4];
    const float* bkv   = (const float*)d_in[5];
    const float* Wproj = (const float*)d_in[6];
    const float* bproj = (const float*)d_in[7];
    float* out = (float*)d_out;

    float *q_ptr, *kv_ptr, *attn_ptr;
    cudaGetSymbolAddress((void**)&q_ptr,    g_q);
    cudaGetSymbolAddress((void**)&kv_ptr,   g_kv);
    cudaGetSymbolAddress((void**)&attn_ptr, g_attn);

    // q = x @ Wq + bq : M=2048, N=1024, K=1024
    {
        dim3 grid(1024 / 128, (BS * NCTX) / 128);
        gemm_bias_kernel<<<grid, 256>>>(x, Wq, bq, q_ptr, BS * NCTX, WIDTH, WIDTH);
    }
    // kv = data @ Wkv + bkv : M=8192, N=2048, K=1024
    {
        dim3 grid((2 * WIDTH) / 128, (BS * NDATA) / 128);
        gemm_bias_kernel<<<grid, 256>>>(data, Wkv, bkv, kv_ptr, BS * NDATA, 2 * WIDTH, WIDTH);
    }
    // attention
    {
        dim3 grid(NCTX / 64, HEADS, BS);
        attn_kernel<<<grid, 256>>>();
    }
    // out = attn @ Wproj + bproj : M=2048, N=1024, K=1024
    {
        dim3 grid(WIDTH / 128, (BS * NCTX) / 128);
        gemm_bias_kernel<<<grid, 256>>>(attn_ptr, Wproj, bproj, out, BS * NCTX, WIDTH, WIDTH);
    }
}

// round 3
// speedup vs baseline: 1.4320x; 1.4320x over previous
#include <cuda_runtime.h>
#include <cuda_bf16.h>
#include <cstdint>

#define WIDTH 1024
#define HEADS 16
#define ACH   64
#define BS    2
#define NCTX  1024
#define NDATA 4096

#define MQ   (BS*NCTX)     // 2048
#define MKV  (BS*NDATA)    // 8192
#define NKV  (2*WIDTH)     // 2048

// ---------------- scratch (allocation-free rule: __device__ globals) --------
__device__ float g_q[MQ*WIDTH];
__device__ float g_kv[MKV*NKV];
__device__ float g_attn[MQ*WIDTH];

__device__ __nv_bfloat16 g_xh[MQ*WIDTH],   g_xl[MQ*WIDTH];
__device__ __nv_bfloat16 g_dh[MKV*WIDTH],  g_dl[MKV*WIDTH];
__device__ __nv_bfloat16 g_wqh[WIDTH*WIDTH],  g_wql[WIDTH*WIDTH];    // [N][K]
__device__ __nv_bfloat16 g_wkvh[NKV*WIDTH],   g_wkvl[NKV*WIDTH];     // [N][K]
__device__ __nv_bfloat16 g_wph[WIDTH*WIDTH],  g_wpl[WIDTH*WIDTH];    // [N][K]
__device__ __nv_bfloat16 g_ah[MQ*WIDTH],   g_al[MQ*WIDTH];

// ---------------- helpers -----------------------------------------------------
__device__ __forceinline__ uint32_t smem_u32(const void* p) {
    uint32_t a;
    asm("{ .reg .u64 t; cvta.to.shared.u64 t, %1; cvt.u32.u64 %0, t; }"
        : "=r"(a) : "l"(p));
    return a;
}

__device__ __forceinline__ void cp16(uint32_t dst, const void* src) {
    asm volatile("cp.async.cg.shared.global [%0], [%1], 16;" :: "r"(dst), "l"(src));
}
__device__ __forceinline__ void cp_commit() {
    asm volatile("cp.async.commit_group;" ::: "memory");
}

#define LDMATRIX_X4(r, addr)                                                    \
    asm volatile("ldmatrix.sync.aligned.m8n8.x4.shared.b16 {%0,%1,%2,%3}, [%4];" \
        : "=r"((r)[0]), "=r"((r)[1]), "=r"((r)[2]), "=r"((r)[3]) : "r"(addr))

#define MMA16816(d, a, b0, b1)                                                  \
    asm volatile("mma.sync.aligned.m16n8k16.row.col.f32.bf16.bf16.f32 "         \
        "{%0,%1,%2,%3},{%4,%5,%6,%7},{%8,%9},{%0,%1,%2,%3};"                    \
        : "+f"((d)[0]), "+f"((d)[1]), "+f"((d)[2]), "+f"((d)[3])                \
        : "r"((a)[0]), "r"((a)[1]), "r"((a)[2]), "r"((a)[3]), "r"(b0), "r"(b1))

// ---------------- conversion kernels ----------------------------------------
__global__ void split_kernel(const float* __restrict__ src,
                             __nv_bfloat16* __restrict__ h,
                             __nv_bfloat16* __restrict__ l, int n)
{
    int i = blockIdx.x * blockDim.x + threadIdx.x;
    if (i < n) {
        float x = src[i];
        __nv_bfloat16 hh = __float2bfloat16(x);
        h[i] = hh;
        l[i] = __float2bfloat16(x - __bfloat162float(hh));
    }
}

// W [Kdim][Ndim] fp32 -> Th/Tl [Ndim][Kdim] bf16
__global__ void transpose_split_kernel(const float* __restrict__ W,
                                       __nv_bfloat16* __restrict__ Th,
                                       __nv_bfloat16* __restrict__ Tl,
                                       int Kdim, int Ndim)
{
    __shared__ float tile[32][33];
    int tx = threadIdx.x, ty = threadIdx.y;
    int n0 = blockIdx.x * 32;
    int k0 = blockIdx.y * 32;
#pragma unroll
    for (int i = 0; i < 4; i++) {
        int k = k0 + ty + i * 8;
        tile[ty + i * 8][tx] = W[(size_t)k * Ndim + n0 + tx];
    }
    __syncthreads();
#pragma unroll
    for (int i = 0; i < 4; i++) {
        int n = n0 + ty + i * 8;
        int k = k0 + tx;
        float v = tile[tx][ty + i * 8];
        __nv_bfloat16 hh = __float2bfloat16(v);
        Th[(size_t)n * Kdim + k] = hh;
        Tl[(size_t)n * Kdim + k] = __float2bfloat16(v - __bfloat162float(hh));
    }
}

// ---------------- bf16x3 HMMA GEMM --------------------------------------------
// C[M,N] = (Ah+Al)[M,K] @ (Bh+Bl)[N,K]^T + bias, fp32 acc.
// 128x128 CTA tile, BK=32, 3-stage cp.async, 8 warps (4m x 2n), warp tile 32x64.
// Smem tile rows padded to 80B: (5*row+seg)%8 hits all 8 16B chunks -> ldmatrix
// conflict-free without extra swizzle.
#define ROWB    80
#define TILE_B  (128*ROWB)        // 10240
#define OFF_AH  0
#define OFF_AL  TILE_B
#define OFF_BH  (2*TILE_B)
#define OFF_BL  (3*TILE_B)
#define STAGE_B (4*TILE_B)        // 40960
#define NSTAGE  3
#define GEMM_SMEM (NSTAGE*STAGE_B)  // 122880

__device__ __forceinline__ void load_stage(
    uint32_t base,
    const __nv_bfloat16* __restrict__ Ah, const __nv_bfloat16* __restrict__ Al,
    const __nv_bfloat16* __restrict__ Bh, const __nv_bfloat16* __restrict__ Bl,
    int K, int bm, int bn, int kc, int tid)
{
    int k0 = kc * 32;
#pragma unroll
    for (int i = 0; i < 2; i++) {
        int idx = tid + i * 256;
        int row = idx >> 2;
        int seg = idx & 3;
        uint32_t off = (uint32_t)(row * ROWB + seg * 16);
        size_t gea = (size_t)(bm + row) * K + k0 + seg * 8;
        size_t geb = (size_t)(bn + row) * K + k0 + seg * 8;
        cp16(base + OFF_AH + off, Ah + gea);
        cp16(base + OFF_AL + off, Al + gea);
        cp16(base + OFF_BH + off, Bh + geb);
        cp16(base + OFF_BL + off, Bl + geb);
    }
}

__global__ void __launch_bounds__(256)
gemm_bf16x3_kernel(const __nv_bfloat16* __restrict__ Ah, const __nv_bfloat16* __restrict__ Al,
                   const __nv_bfloat16* __restrict__ Bh, const __nv_bfloat16* __restrict__ Bl,
                   const float* __restrict__ bias, float* __restrict__ C,
                   int M, int N, int K)
{
    extern __shared__ char smem[];
    const uint32_t sb = smem_u32(smem);

    const int tid  = threadIdx.x;
    const int lane = tid & 31;
    const int wid  = tid >> 5;
    const int warp_m = wid & 3;     // 0..3 -> 32-row slices
    const int warp_n = wid >> 2;    // 0..1 -> 64-col slices
    const int bm = blockIdx.y * 128;
    const int bn = blockIdx.x * 128;

    // per-thread ldmatrix byte offsets (within a tile)
    const uint32_t a_byte = (uint32_t)((warp_m * 32 + (lane & 15)) * ROWB + ((lane >> 4) << 4));
    const uint32_t b_byte = (uint32_t)((warp_n * 64 + (lane & 7) + ((lane >> 4) << 3)) * ROWB
                                       + (((lane >> 3) & 1) << 4));

    float acc[2][8][4];
#pragma unroll
    for (int mi = 0; mi < 2; mi++)
#pragma unroll
        for (int j = 0; j < 8; j++)
#pragma unroll
            for (int r = 0; r < 4; r++) acc[mi][j][r] = 0.0f;

    const int nchunk = K >> 5;   // K/32

    // prologue: prefetch 3 stages
#pragma unroll
    for (int s = 0; s < NSTAGE; s++) {
        load_stage(sb + s * STAGE_B, Ah, Al, Bh, Bl, K, bm, bn, s, tid);
        cp_commit();
    }

    for (int kc = 0; kc < nchunk; kc++) {
        int rem = nchunk - kc - 1;
        if (rem >= 2)      asm volatile("cp.async.wait_group 2;" ::: "memory");
        else if (rem == 1) asm volatile("cp.async.wait_group 1;" ::: "memory");
        else               asm volatile("cp.async.wait_group 0;" ::: "memory");
        __syncthreads();

        uint32_t sbase;
        {
            int st = kc % NSTAGE;
            sbase = sb + (uint32_t)st * STAGE_B;
        }

#pragma unroll
        for (int ks = 0; ks < 2; ks++) {
            uint32_t kofs = (uint32_t)(ks * 32);
            uint32_t ahr[2][4], alr[2][4];
#pragma unroll
            for (int mi = 0; mi < 2; mi++) {
                uint32_t ao = a_byte + (uint32_t)(mi * 16 * ROWB) + kofs;
                LDMATRIX_X4(ahr[mi], sbase + OFF_AH + ao);
                LDMATRIX_X4(alr[mi], sbase + OFF_AL + ao);
            }
            uint32_t bhr[4][4], blr[4][4];
#pragma unroll
            for (int ni = 0; ni < 4; ni++) {
                uint32_t bo = b_byte + (uint32_t)(ni * 16 * ROWB) + kofs;
                LDMATRIX_X4(bhr[ni], sbase + OFF_BH + bo);
                LDMATRIX_X4(blr[ni], sbase + OFF_BL + bo);
            }
#pragma unroll
            for (int mi = 0; mi < 2; mi++)
#pragma unroll
                for (int ni = 0; ni < 4; ni++) {
                    MMA16816(acc[mi][2 * ni],     ahr[mi], bhr[ni][0], bhr[ni][1]);
                    MMA16816(acc[mi][2 * ni + 1], ahr[mi], bhr[ni][2], bhr[ni][3]);
                    MMA16816(acc[mi][2 * ni],     ahr[mi], blr[ni][0], blr[ni][1]);
                    MMA16816(acc[mi][2 * ni + 1], ahr[mi], blr[ni][2], blr[ni][3]);
                    MMA16816(acc[mi][2 * ni],     alr[mi], bhr[ni][0], bhr[ni][1]);
                    MMA16816(acc[mi][2 * ni + 1], alr[mi], bhr[ni][2], bhr[ni][3]);
                }
        }

        __syncthreads();
        int kn = kc + NSTAGE;
        if (kn < nchunk) {
            load_stage(sbase, Ah, Al, Bh, Bl, K, bm, bn, kn, tid);
            cp_commit();
        }
    }

    // epilogue: direct register -> global stores (float2), add bias
    const int m_base = bm + warp_m * 32;
    const int n_base = bn + warp_n * 64;
    const int rq = lane >> 2;        // 0..7
    const int cq = (lane & 3) * 2;   // 0,2,4,6
#pragma unroll
    for (int mi = 0; mi < 2; mi++) {
#pragma unroll
        for (int j = 0; j < 8; j++) {
            int col = n_base + j * 8 + cq;
            float b0 = bias[col];
            float b1 = bias[col + 1];
            int r0 = m_base + mi * 16 + rq;
            float2 v0 = make_float2(acc[mi][j][0] + b0, acc[mi][j][1] + b1);
            float2 v1 = make_float2(acc[mi][j][2] + b0, acc[mi][j][3] + b1);
            *(float2*)&C[(size_t)r0 * N + col]       = v0;
            *(float2*)&C[(size_t)(r0 + 8) * N + col] = v1;
        }
    }
}

// ---------------- flash attention (SIMT fp32, unchanged) ---------------------
__global__ void __launch_bounds__(256) attn_kernel()
{
    __shared__ float Qs[64][64];
    __shared__ float KPs[64][64];
    __shared__ float Vs[64][64];

    const int b  = blockIdx.z;
    const int h  = blockIdx.y;
    const int t0 = blockIdx.x * 64;

    const int tid = threadIdx.x;
    const int x = tid & 15;
    const int y = tid >> 4;

#pragma unroll
    for (int it = 0; it < 4; it++) {
        int r  = (tid >> 4) + it * 16;
        int c4 = (tid & 15) * 4;
        float4 v = *(const float4*)&g_q[(b * NCTX + t0 + r) * WIDTH + h * ACH + c4];
        Qs[c4 + 0][r] = v.x;
        Qs[c4 + 1][r] = v.y;
        Qs[c4 + 2][r] = v.z;
        Qs[c4 + 3][r] = v.w;
    }

    float m[4], l[4], o[4][4];
#pragma unroll
    for (int i = 0; i < 4; i++) {
        m[i] = -1e30f;
        l[i] = 0.0f;
#pragma unroll
        for (int j = 0; j < 4; j++) o[i][j] = 0.0f;
    }

    for (int s0 = 0; s0 < NDATA; s0 += 64) {
        __syncthreads();
#pragma unroll
        for (int it = 0; it < 4; it++) {
            int s  = (tid >> 4) + it * 16;
            int c4 = (tid & 15) * 4;
            const float* kvrow = &g_kv[(size_t)(b * NDATA + s0 + s) * (2 * WIDTH) + h * 2 * ACH];
            float4 kvk = *(const float4*)(kvrow + c4);
            KPs[c4 + 0][s] = kvk.x;
            KPs[c4 + 1][s] = kvk.y;
            KPs[c4 + 2][s] = kvk.z;
            KPs[c4 + 3][s] = kvk.w;
            float4 vv = *(const float4*)(kvrow + ACH + c4);
            *(float4*)&Vs[s][c4] = vv;
        }
        __syncthreads();

        float sacc[4][4];
#pragma unroll
        for (int i = 0; i < 4; i++)
#pragma unroll
            for (int j = 0; j < 4; j++) sacc[i][j] = 0.0f;

#pragma unroll 16
        for (int c = 0; c < 64; c++) {
            float4 a4 = *(const float4*)&Qs[c][y * 4];
            float4 b4 = *(const float4*)&KPs[c][x * 4];
            float a[4] = {a4.x, a4.y, a4.z, a4.w};
            float bb[4] = {b4.x, b4.y, b4.z, b4.w};
#pragma unroll
            for (int i = 0; i < 4; i++)
#pragma unroll
                for (int j = 0; j < 4; j++)
                    sacc[i][j] += a[i] * bb[j];
        }
#pragma unroll
        for (int i = 0; i < 4; i++)
#pragma unroll
            for (int j = 0; j < 4; j++) sacc[i][j] *= 0.125f;

        float p[4][4];
#pragma unroll
        for (int i = 0; i < 4; i++) {
            float v = fmaxf(fmaxf(sacc[i][0], sacc[i][1]),
                            fmaxf(sacc[i][2], sacc[i][3]));
            v = fmaxf(v, __shfl_xor_sync(0xffffffffu, v, 1));
            v = fmaxf(v, __shfl_xor_sync(0xffffffffu, v, 2));
            v = fmaxf(v, __shfl_xor_sync(0xffffffffu, v, 4));
            v = fmaxf(v, __shfl_xor_sync(0xffffffffu, v, 8));
            float mn = fmaxf(m[i], v);
            float corr = __expf(m[i] - mn);
            m[i] = mn;
            l[i] *= corr;
#pragma unroll
            for (int j = 0; j < 4; j++) {
                p[i][j] = __expf(sacc[i][j] - mn);
                o[i][j] *= corr;
            }
            float rs = p[i][0] + p[i][1] + p[i][2] + p[i][3];
            rs += __shfl_xor_sync(0xffffffffu, rs, 1);
            rs += __shfl_xor_sync(0xffffffffu, rs, 2);
            rs += __shfl_xor_sync(0xffffffffu, rs, 4);
            rs += __shfl_xor_sync(0xffffffffu, rs, 8);
            l[i] += rs;
        }

        __syncthreads();
#pragma unroll
        for (int i = 0; i < 4; i++)
#pragma unroll
            for (int j = 0; j < 4; j++)
                KPs[y * 4 + i][x * 4 + j] = p[i][j];
        __syncthreads();

#pragma unroll 16
        for (int s = 0; s < 64; s++) {
            float4 b4 = *(const float4*)&Vs[s][x * 4];
            float bb[4] = {b4.x, b4.y, b4.z, b4.w};
            float pa[4];
#pragma unroll
            for (int i = 0; i < 4; i++) pa[i] = KPs[y * 4 + i][s];
#pragma unroll
            for (int i = 0; i < 4; i++)
#pragma unroll
                for (int j = 0; j < 4; j++)
                    o[i][j] += pa[i] * bb[j];
        }
    }

#pragma unroll
    for (int i = 0; i < 4; i++) {
        float inv = 1.0f / l[i];
        int t = t0 + y * 4 + i;
#pragma unroll
        for (int j = 0; j < 4; j++) {
            g_attn[(size_t)(b * NCTX + t) * WIDTH + h * ACH + x * 4 + j] = o[i][j] * inv;
        }
    }
}

// ---------------- launch ------------------------------------------------------
extern "C" void kernel_launch(void* const* d_in, const int* in_sizes, int n_in,
                              void* d_out, int out_size)
{
    (void)in_sizes; (void)n_in; (void)out_size;

    const float* x     = (const float*)d_in[0];
    const float* data  = (const float*)d_in[1];
    const float* Wq    = (const float*)d_in[2];
    const float* bq    = (const float*)d_in[3];
    const float* Wkv   = (const float*)d_in[4];
    const float* bkv   = (const float*)d_in[5];
    const float* Wproj = (const float*)d_in[6];
    const float* bproj = (const float*)d_in[7];
    float* out = (float*)d_out;

    float *q_ptr, *kv_ptr, *attn_ptr;
    cudaGetSymbolAddress((void**)&q_ptr,    g_q);
    cudaGetSymbolAddress((void**)&kv_ptr,   g_kv);
    cudaGetSymbolAddress((void**)&attn_ptr, g_attn);

    __nv_bfloat16 *xh, *xl, *dh, *dl, *wqh, *wql, *wkvh, *wkvl, *wph, *wpl, *ah, *al;
    cudaGetSymbolAddress((void**)&xh,  g_xh);  cudaGetSymbolAddress((void**)&xl,  g_xl);
    cudaGetSymbolAddress((void**)&dh,  g_dh);  cudaGetSymbolAddress((void**)&dl,  g_dl);
    cudaGetSymbolAddress((void**)&wqh, g_wqh); cudaGetSymbolAddress((void**)&wql, g_wql);
    cudaGetSymbolAddress((void**)&wkvh,g_wkvh);cudaGetSymbolAddress((void**)&wkvl,g_wkvl);
    cudaGetSymbolAddress((void**)&wph, g_wph); cudaGetSymbolAddress((void**)&wpl, g_wpl);
    cudaGetSymbolAddress((void**)&ah,  g_ah);  cudaGetSymbolAddress((void**)&al,  g_al);

    cudaFuncSetAttribute(gemm_bf16x3_kernel,
                         cudaFuncAttributeMaxDynamicSharedMemorySize, GEMM_SMEM);

    // 1. splits & weight transposes
    split_kernel<<<(MQ * WIDTH) / 256, 256>>>(x, xh, xl, MQ * WIDTH);
    split_kernel<<<(MKV * WIDTH) / 256, 256>>>(data, dh, dl, MKV * WIDTH);
    {
        dim3 blk(32, 8);
        transpose_split_kernel<<<dim3(WIDTH / 32, WIDTH / 32), blk>>>(Wq, wqh, wql, WIDTH, WIDTH);
        transpose_split_kernel<<<dim3(NKV / 32, WIDTH / 32), blk>>>(Wkv, wkvh, wkvl, WIDTH, NKV);
        transpose_split_kernel<<<dim3(WIDTH / 32, WIDTH / 32), blk>>>(Wproj, wph, wpl, WIDTH, WIDTH);
    }

    // 2. q = x @ Wq + bq
    gemm_bf16x3_kernel<<<dim3(WIDTH / 128, MQ / 128), 256, GEMM_SMEM>>>(
        xh, xl, wqh, wql, bq, q_ptr, MQ, WIDTH, WIDTH);

    // 3. kv = data @ Wkv + bkv
    gemm_bf16x3_kernel<<<dim3(NKV / 128, MKV / 128), 256, GEMM_SMEM>>>(
        dh, dl, wkvh, wkvl, bkv, kv_ptr, MKV, NKV, WIDTH);

    // 4. attention
    attn_kernel<<<dim3(NCTX / 64, HEADS, BS), 256>>>();

    // 5. split attention output
    split_kernel<<<(MQ * WIDTH) / 256, 256>>>(attn_ptr, ah, al, MQ * WIDTH);

    // 6. out = attn @ Wproj + bproj
    gemm_bf16x3_kernel<<<dim3(WIDTH / 128, MQ / 128), 256, GEMM_SMEM>>>(
        ah, al, wph, wpl, bproj, out, MQ, WIDTH, WIDTH);
}

// round 4
// speedup vs baseline: 2.9844x; 2.0841x over previous
#include <cuda_runtime.h>
#include <cuda_bf16.h>
#include <cstdint>

#define WIDTH 1024
#define HEADS 16
#define ACH   64
#define BS    2
#define NCTX  1024
#define NDATA 4096

#define MQ   (BS*NCTX)     // 2048
#define MKV  (BS*NDATA)    // 8192
#define NKV  (2*WIDTH)     // 2048

// ---------------- scratch (allocation-free rule: __device__ globals) --------
__device__ __nv_bfloat16 g_xh[MQ*WIDTH],   g_xl[MQ*WIDTH];
__device__ __nv_bfloat16 g_dh[MKV*WIDTH],  g_dl[MKV*WIDTH];
__device__ __nv_bfloat16 g_wqh[WIDTH*WIDTH],  g_wql[WIDTH*WIDTH];    // [N][K]
__device__ __nv_bfloat16 g_wkvh[NKV*WIDTH],   g_wkvl[NKV*WIDTH];     // [N][K]
__device__ __nv_bfloat16 g_wph[WIDTH*WIDTH],  g_wpl[WIDTH*WIDTH];    // [N][K]
__device__ __nv_bfloat16 g_qh[MQ*WIDTH],   g_ql[MQ*WIDTH];
__device__ __nv_bfloat16 g_kvh[MKV*NKV],   g_kvl[MKV*NKV];
__device__ __nv_bfloat16 g_ah[MQ*WIDTH],   g_al[MQ*WIDTH];

// ---------------- helpers -----------------------------------------------------
__device__ __forceinline__ uint32_t smem_u32(const void* p) {
    uint32_t a;
    asm("{ .reg .u64 t; cvta.to.shared.u64 t, %1; cvt.u32.u64 %0, t; }"
        : "=r"(a) : "l"(p));
    return a;
}

__device__ __forceinline__ void cp16(uint32_t dst, const void* src) {
    asm volatile("cp.async.cg.shared.global [%0], [%1], 16;" :: "r"(dst), "l"(src));
}
__device__ __forceinline__ void cp_commit() {
    asm volatile("cp.async.commit_group;" ::: "memory");
}

#define LDMATRIX_X4(r, addr)                                                    \
    asm volatile("ldmatrix.sync.aligned.m8n8.x4.shared.b16 {%0,%1,%2,%3}, [%4];" \
        : "=r"((r)[0]), "=r"((r)[1]), "=r"((r)[2]), "=r"((r)[3]) : "r"(addr))

#define LDMATRIX_X4T(r, addr)                                                   \
    asm volatile("ldmatrix.sync.aligned.m8n8.x4.trans.shared.b16 {%0,%1,%2,%3}, [%4];" \
        : "=r"((r)[0]), "=r"((r)[1]), "=r"((r)[2]), "=r"((r)[3]) : "r"(addr))

#define MMA16816(d, a, b0, b1)                                                  \
    asm volatile("mma.sync.aligned.m16n8k16.row.col.f32.bf16.bf16.f32 "         \
        "{%0,%1,%2,%3},{%4,%5,%6,%7},{%8,%9},{%0,%1,%2,%3};"                    \
        : "+f"((d)[0]), "+f"((d)[1]), "+f"((d)[2]), "+f"((d)[3])                \
        : "r"((a)[0]), "r"((a)[1]), "r"((a)[2]), "r"((a)[3]), "r"(b0), "r"(b1))

__device__ __forceinline__ void split2(float a, float b, uint32_t& hv, uint32_t& lv) {
    __nv_bfloat16 ah = __float2bfloat16(a);
    __nv_bfloat16 bh = __float2bfloat16(b);
    __nv_bfloat162 hp(ah, bh);
    hv = *reinterpret_cast<uint32_t*>(&hp);
    __nv_bfloat162 lp(__float2bfloat16(a - __bfloat162float(ah)),
                      __float2bfloat16(b - __bfloat162float(bh)));
    lv = *reinterpret_cast<uint32_t*>(&lp);
}

// ---------------- conversion kernels ----------------------------------------
__global__ void split_kernel(const float* __restrict__ src,
                             __nv_bfloat16* __restrict__ h,
                             __nv_bfloat16* __restrict__ l, int n)
{
    int i = blockIdx.x * blockDim.x + threadIdx.x;
    if (i < n) {
        float x = src[i];
        __nv_bfloat16 hh = __float2bfloat16(x);
        h[i] = hh;
        l[i] = __float2bfloat16(x - __bfloat162float(hh));
    }
}

// W [Kdim][Ndim] fp32 -> Th/Tl [Ndim][Kdim] bf16
__global__ void transpose_split_kernel(const float* __restrict__ W,
                                       __nv_bfloat16* __restrict__ Th,
                                       __nv_bfloat16* __restrict__ Tl,
                                       int Kdim, int Ndim)
{
    __shared__ float tile[32][33];
    int tx = threadIdx.x, ty = threadIdx.y;
    int n0 = blockIdx.x * 32;
    int k0 = blockIdx.y * 32;
#pragma unroll
    for (int i = 0; i < 4; i++) {
        int k = k0 + ty + i * 8;
        tile[ty + i * 8][tx] = W[(size_t)k * Ndim + n0 + tx];
    }
    __syncthreads();
#pragma unroll
    for (int i = 0; i < 4; i++) {
        int n = n0 + ty + i * 8;
        int k = k0 + tx;
        float v = tile[tx][ty + i * 8];
        __nv_bfloat16 hh = __float2bfloat16(v);
        Th[(size_t)n * Kdim + k] = hh;
        Tl[(size_t)n * Kdim + k] = __float2bfloat16(v - __bfloat162float(hh));
    }
}

// ---------------- bf16x3 HMMA GEMM --------------------------------------------
// C = (Ah+Al)[M,K] @ (Bh+Bl)[N,K]^T + bias, fp32 acc.
// Output either fp32 C, or split bf16 (Ch, Cl).
#define ROWB    80
#define TILE_B  (128*ROWB)
#define OFF_AH  0
#define OFF_AL  TILE_B
#define OFF_BH  (2*TILE_B)
#define OFF_BL  (3*TILE_B)
#define STAGE_B (4*TILE_B)
#define NSTAGE  3
#define GEMM_SMEM (NSTAGE*STAGE_B)  // 122880

__device__ __forceinline__ void load_stage(
    uint32_t base,
    const __nv_bfloat16* __restrict__ Ah, const __nv_bfloat16* __restrict__ Al,
    const __nv_bfloat16* __restrict__ Bh, const __nv_bfloat16* __restrict__ Bl,
    int K, int bm, int bn, int kc, int tid)
{
    int k0 = kc * 32;
#pragma unroll
    for (int i = 0; i < 2; i++) {
        int idx = tid + i * 256;
        int row = idx >> 2;
        int seg = idx & 3;
        uint32_t off = (uint32_t)(row * ROWB + seg * 16);
        size_t gea = (size_t)(bm + row) * K + k0 + seg * 8;
        size_t geb = (size_t)(bn + row) * K + k0 + seg * 8;
        cp16(base + OFF_AH + off, Ah + gea);
        cp16(base + OFF_AL + off, Al + gea);
        cp16(base + OFF_BH + off, Bh + geb);
        cp16(base + OFF_BL + off, Bl + geb);
    }
}

__global__ void __launch_bounds__(256)
gemm_bf16x3_kernel(const __nv_bfloat16* __restrict__ Ah, const __nv_bfloat16* __restrict__ Al,
                   const __nv_bfloat16* __restrict__ Bh, const __nv_bfloat16* __restrict__ Bl,
                   const float* __restrict__ bias,
                   float* __restrict__ C,
                   __nv_bfloat16* __restrict__ Ch, __nv_bfloat16* __restrict__ Cl,
                   int M, int N, int K)
{
    extern __shared__ char smem[];
    const uint32_t sb = smem_u32(smem);

    const int tid  = threadIdx.x;
    const int lane = tid & 31;
    const int wid  = tid >> 5;
    const int warp_m = wid & 3;
    const int warp_n = wid >> 2;
    const int bm = blockIdx.y * 128;
    const int bn = blockIdx.x * 128;

    const uint32_t a_byte = (uint32_t)((warp_m * 32 + (lane & 15)) * ROWB + ((lane >> 4) << 4));
    const uint32_t b_byte = (uint32_t)((warp_n * 64 + (lane & 7) + ((lane >> 4) << 3)) * ROWB
                                       + (((lane >> 3) & 1) << 4));

    float acc[2][8][4];
#pragma unroll
    for (int mi = 0; mi < 2; mi++)
#pragma unroll
        for (int j = 0; j < 8; j++)
#pragma unroll
            for (int r = 0; r < 4; r++) acc[mi][j][r] = 0.0f;

    const int nchunk = K >> 5;

#pragma unroll
    for (int s = 0; s < NSTAGE; s++) {
        load_stage(sb + s * STAGE_B, Ah, Al, Bh, Bl, K, bm, bn, s, tid);
        cp_commit();
    }

    for (int kc = 0; kc < nchunk; kc++) {
        int rem = nchunk - kc - 1;
        if (rem >= 2)      asm volatile("cp.async.wait_group 2;" ::: "memory");
        else if (rem == 1) asm volatile("cp.async.wait_group 1;" ::: "memory");
        else               asm volatile("cp.async.wait_group 0;" ::: "memory");
        __syncthreads();

        uint32_t sbase = sb + (uint32_t)(kc % NSTAGE) * STAGE_B;

#pragma unroll
        for (int ks = 0; ks < 2; ks++) {
            uint32_t kofs = (uint32_t)(ks * 32);
            uint32_t ahr[2][4], alr[2][4];
#pragma unroll
            for (int mi = 0; mi < 2; mi++) {
                uint32_t ao = a_byte + (uint32_t)(mi * 16 * ROWB) + kofs;
                LDMATRIX_X4(ahr[mi], sbase + OFF_AH + ao);
                LDMATRIX_X4(alr[mi], sbase + OFF_AL + ao);
            }
#pragma unroll
            for (int ni = 0; ni < 4; ni++) {
                uint32_t bo = b_byte + (uint32_t)(ni * 16 * ROWB) + kofs;
                uint32_t bhr[4], blr[4];
                LDMATRIX_X4(bhr, sbase + OFF_BH + bo);
                LDMATRIX_X4(blr, sbase + OFF_BL + bo);
#pragma unroll
                for (int mi = 0; mi < 2; mi++) {
                    MMA16816(acc[mi][2 * ni],     ahr[mi], bhr[0], bhr[1]);
                    MMA16816(acc[mi][2 * ni + 1], ahr[mi], bhr[2], bhr[3]);
                    MMA16816(acc[mi][2 * ni],     ahr[mi], blr[0], blr[1]);
                    MMA16816(acc[mi][2 * ni + 1], ahr[mi], blr[2], blr[3]);
                    MMA16816(acc[mi][2 * ni],     alr[mi], bhr[0], bhr[1]);
                    MMA16816(acc[mi][2 * ni + 1], alr[mi], bhr[2], bhr[3]);
                }
            }
        }

        __syncthreads();
        int kn = kc + NSTAGE;
        if (kn < nchunk) {
            load_stage(sbase, Ah, Al, Bh, Bl, K, bm, bn, kn, tid);
            cp_commit();
        }
    }

    const int m_base = bm + warp_m * 32;
    const int n_base = bn + warp_n * 64;
    const int rq = lane >> 2;
    const int cq = (lane & 3) * 2;
#pragma unroll
    for (int mi = 0; mi < 2; mi++) {
#pragma unroll
        for (int j = 0; j < 8; j++) {
            int col = n_base + j * 8 + cq;
            float b0 = bias[col];
            float b1 = bias[col + 1];
            int r0 = m_base + mi * 16 + rq;
            float v0 = acc[mi][j][0] + b0, v1 = acc[mi][j][1] + b1;
            float v2 = acc[mi][j][2] + b0, v3 = acc[mi][j][3] + b1;
            if (Ch) {
                uint32_t hv, lv;
                split2(v0, v1, hv, lv);
                *(uint32_t*)&Ch[(size_t)r0 * N + col] = hv;
                *(uint32_t*)&Cl[(size_t)r0 * N + col] = lv;
                split2(v2, v3, hv, lv);
                *(uint32_t*)&Ch[(size_t)(r0 + 8) * N + col] = hv;
                *(uint32_t*)&Cl[(size_t)(r0 + 8) * N + col] = lv;
            } else {
                *(float2*)&C[(size_t)r0 * N + col]       = make_float2(v0, v1);
                *(float2*)&C[(size_t)(r0 + 8) * N + col] = make_float2(v2, v3);
            }
        }
    }
}

// ---------------- HMMA flash attention ----------------------------------------
// One CTA: 128 query rows for one (b, h). 8 warps, each owns m16 rows.
// S = QK^T via bf16x3; online softmax (base-2); PV via bf16x3 with in-register
// P fragment conversion. K natural [s][c] (B frag), V natural [s][c] with
// ldmatrix.trans.
#define APITCH 144                       // bytes per 64-ch bf16 row (padded)
#define AQH 0
#define AQL (128*APITCH)                 // 18432
#define AST (2*128*APITCH)               // 36864
#define TKH 0
#define TKL (64*APITCH)                  // 9216
#define TVH (128*APITCH)
#define TVL (192*APITCH)
#define ASTAGE (256*APITCH)              // 36864
#define ATTN_SMEM (AST + 2*ASTAGE)       // 110592

__device__ __forceinline__ void load_kv_stage(uint32_t dst, int b, int h, int s0, int tid)
{
#pragma unroll
    for (int i = 0; i < 2; i++) {
        int idx = tid + i * 256;
        int row = idx >> 3;
        int seg = idx & 7;
        size_t base = (size_t)(b * NDATA + s0 + row) * NKV + h * 128 + seg * 8;
        uint32_t so = (uint32_t)(row * APITCH + seg * 16);
        cp16(dst + TKH + so, g_kvh + base);
        cp16(dst + TKL + so, g_kvl + base);
        cp16(dst + TVH + so, g_kvh + base + 64);
        cp16(dst + TVL + so, g_kvl + base + 64);
    }
}

__global__ void __launch_bounds__(256)
attn_hmma_kernel()
{
    extern __shared__ char smem[];
    const uint32_t sb = smem_u32(smem);

    const int tid  = threadIdx.x;
    const int lane = tid & 31;
    const int wid  = tid >> 5;
    const int qt = blockIdx.x;
    const int h  = blockIdx.y;
    const int b  = blockIdx.z;
    const int t0 = qt * 128;

    // ---- load Q tile (group 0) ----
#pragma unroll
    for (int i = 0; i < 4; i++) {
        int idx = tid + i * 256;
        int row = idx >> 3;
        int seg = idx & 7;
        size_t go = (size_t)(b * NCTX + t0 + row) * WIDTH + h * ACH + seg * 8;
        uint32_t so = (uint32_t)(row * APITCH + seg * 16);
        cp16(sb + AQH + so, g_qh + go);
        cp16(sb + AQL + so, g_ql + go);
    }
    cp_commit();
    // ---- stages 0, 1 ----
    load_kv_stage(sb + AST, b, h, 0, tid);
    cp_commit();
    load_kv_stage(sb + AST + ASTAGE, b, h, 64, tid);
    cp_commit();

    // Q fragments (held in registers for the whole kernel)
    asm volatile("cp.async.wait_group 2;" ::: "memory");
    __syncthreads();
    uint32_t qhf[4][4], qlf[4][4];
    {
        uint32_t qa = (uint32_t)((wid * 16 + (lane & 15)) * APITCH + ((lane >> 4) << 4));
#pragma unroll
        for (int kc = 0; kc < 4; kc++) {
            LDMATRIX_X4(qhf[kc], sb + AQH + qa + kc * 32);
            LDMATRIX_X4(qlf[kc], sb + AQL + qa + kc * 32);
        }
    }

    const uint32_t kb = (uint32_t)(((lane & 7) + ((lane >> 4) << 3)) * APITCH
                                   + (((lane >> 3) & 1) << 4));
    const uint32_t vb = (uint32_t)((lane & 15) * APITCH + ((lane >> 4) << 4));

    float m2[2] = {-1e30f, -1e30f};
    float l[2]  = {0.0f, 0.0f};
    float o[8][4];
#pragma unroll
    for (int j = 0; j < 8; j++)
#pragma unroll
        for (int e = 0; e < 4; e++) o[j][e] = 0.0f;

    const float CS = 0.125f * 1.44269504f;

    const int NCHUNK = NDATA / 64;    // 64
    for (int sc = 0; sc < NCHUNK; sc++) {
        if (sc + 1 < NCHUNK) asm volatile("cp.async.wait_group 1;" ::: "memory");
        else                 asm volatile("cp.async.wait_group 0;" ::: "memory");
        __syncthreads();

        uint32_t st = sb + AST + (uint32_t)(sc & 1) * ASTAGE;

        // ---- S = Q K^T (bf16x3) ----
        float sacc[8][4];
#pragma unroll
        for (int j = 0; j < 8; j++)
#pragma unroll
            for (int e = 0; e < 4; e++) sacc[j][e] = 0.0f;

#pragma unroll
        for (int kc = 0; kc < 4; kc++) {
#pragma unroll
            for (int g = 0; g < 4; g++) {
                uint32_t ko = kb + (uint32_t)(g * 16 * APITCH) + kc * 32;
                uint32_t khf[4], klf[4];
                LDMATRIX_X4(khf, st + TKH + ko);
                LDMATRIX_X4(klf, st + TKL + ko);
                MMA16816(sacc[2 * g],     qhf[kc], khf[0], khf[1]);
                MMA16816(sacc[2 * g + 1], qhf[kc], khf[2], khf[3]);
                MMA16816(sacc[2 * g],     qhf[kc], klf[0], klf[1]);
                MMA16816(sacc[2 * g + 1], qhf[kc], klf[2], klf[3]);
                MMA16816(sacc[2 * g],     qlf[kc], khf[0], khf[1]);
                MMA16816(sacc[2 * g + 1], qlf[kc], khf[2], khf[3]);
            }
        }

        // ---- online softmax (base-2, scale folded) ----
        float mx0 = -1e30f, mx1 = -1e30f;
#pragma unroll
        for (int j = 0; j < 8; j++) {
            mx0 = fmaxf(mx0, fmaxf(sacc[j][0], sacc[j][1]));
            mx1 = fmaxf(mx1, fmaxf(sacc[j][2], sacc[j][3]));
        }
        mx0 *= CS; mx1 *= CS;
        mx0 = fmaxf(mx0, __shfl_xor_sync(0xffffffffu, mx0, 1));
        mx0 = fmaxf(mx0, __shfl_xor_sync(0xffffffffu, mx0, 2));
        mx1 = fmaxf(mx1, __shfl_xor_sync(0xffffffffu, mx1, 1));
        mx1 = fmaxf(mx1, __shfl_xor_sync(0xffffffffu, mx1, 2));
        float mn0 = fmaxf(m2[0], mx0), mn1 = fmaxf(m2[1], mx1);
        float c0 = exp2f(m2[0] - mn0), c1 = exp2f(m2[1] - mn1);
        m2[0] = mn0; m2[1] = mn1;

        float rs0 = 0.0f, rs1 = 0.0f;
#pragma unroll
        for (int j = 0; j < 8; j++) {
            float p0 = exp2f(fmaf(sacc[j][0], CS, -mn0));
            float p1 = exp2f(fmaf(sacc[j][1], CS, -mn0));
            float p2 = exp2f(fmaf(sacc[j][2], CS, -mn1));
            float p3 = exp2f(fmaf(sacc[j][3], CS, -mn1));
            sacc[j][0] = p0; sacc[j][1] = p1; sacc[j][2] = p2; sacc[j][3] = p3;
            rs0 += p0 + p1; rs1 += p2 + p3;
        }
        rs0 += __shfl_xor_sync(0xffffffffu, rs0, 1);
        rs0 += __shfl_xor_sync(0xffffffffu, rs0, 2);
        rs1 += __shfl_xor_sync(0xffffffffu, rs1, 1);
        rs1 += __shfl_xor_sync(0xffffffffu, rs1, 2);
        l[0] = l[0] * c0 + rs0;
        l[1] = l[1] * c1 + rs1;
#pragma unroll
        for (int j = 0; j < 8; j++) {
            o[j][0] *= c0; o[j][1] *= c0;
            o[j][2] *= c1; o[j][3] *= c1;
        }

        // ---- pack P into A fragments (bf16 hi + residual lo) ----
        uint32_t ph[4][4], pl[4][4];
#pragma unroll
        for (int kc = 0; kc < 4; kc++) {
            int j0 = 2 * kc, j1 = 2 * kc + 1;
            split2(sacc[j0][0], sacc[j0][1], ph[kc][0], pl[kc][0]);
            split2(sacc[j0][2], sacc[j0][3], ph[kc][1], pl[kc][1]);
            split2(sacc[j1][0], sacc[j1][1], ph[kc][2], pl[kc][2]);
            split2(sacc[j1][2], sacc[j1][3], ph[kc][3], pl[kc][3]);
        }

        // ---- O += P V (bf16x3) ----
#pragma unroll
        for (int kc = 0; kc < 4; kc++) {
#pragma unroll
            for (int g = 0; g < 4; g++) {
                uint32_t vo = vb + (uint32_t)(kc * 16 * APITCH) + g * 32;
                uint32_t vhf[4], vlf[4];
                LDMATRIX_X4T(vhf, st + TVH + vo);
                LDMATRIX_X4T(vlf, st + TVL + vo);
                MMA16816(o[2 * g],     ph[kc], vhf[0], vhf[1]);
                MMA16816(o[2 * g + 1], ph[kc], vhf[2], vhf[3]);
                MMA16816(o[2 * g],     ph[kc], vlf[0], vlf[1]);
                MMA16816(o[2 * g + 1], ph[kc], vlf[2], vlf[3]);
                MMA16816(o[2 * g],     pl[kc], vhf[0], vhf[1]);
                MMA16816(o[2 * g + 1], pl[kc], vhf[2], vhf[3]);
            }
        }

        // ---- prefetch next stage ----
        __syncthreads();
        if (sc + 2 < NCHUNK) {
            load_kv_stage(st, b, h, (sc + 2) * 64, tid);
            cp_commit();
        }
    }

    // ---- epilogue: normalize, split, store ----
    float inv0 = 1.0f / l[0];
    float inv1 = 1.0f / l[1];
    int r = t0 + wid * 16 + (lane >> 2);
    int cq = (lane & 3) * 2;
#pragma unroll
    for (int j = 0; j < 8; j++) {
        int col = h * ACH + j * 8 + cq;
        uint32_t hv, lv;
        split2(o[j][0] * inv0, o[j][1] * inv0, hv, lv);
        *(uint32_t*)&g_ah[(size_t)(b * NCTX + r) * WIDTH + col] = hv;
        *(uint32_t*)&g_al[(size_t)(b * NCTX + r) * WIDTH + col] = lv;
        split2(o[j][2] * inv1, o[j][3] * inv1, hv, lv);
        *(uint32_t*)&g_ah[(size_t)(b * NCTX + r + 8) * WIDTH + col] = hv;
        *(uint32_t*)&g_al[(size_t)(b * NCTX + r + 8) * WIDTH + col] = lv;
    }
}

// ---------------- launch ------------------------------------------------------
extern "C" void kernel_launch(void* const* d_in, const int* in_sizes, int n_in,
                              void* d_out, int out_size)
{
    (void)in_sizes; (void)n_in; (void)out_size;

    const float* x     = (const float*)d_in[0];
    const float* data  = (const float*)d_in[1];
    const float* Wq    = (const float*)d_in[2];
    const float* bq    = (const float*)d_in[3];
    const float* Wkv   = (const float*)d_in[4];
    const float* bkv   = (const float*)d_in[5];
    const float* Wproj = (const float*)d_in[6];
    const float* bproj = (const float*)d_in[7];
    float* out = (float*)d_out;

    __nv_bfloat16 *xh, *xl, *dh, *dl, *wqh, *wql, *wkvh, *wkvl, *wph, *wpl;
    __nv_bfloat16 *qh, *ql, *kvh, *kvl, *ah, *al;
    cudaGetSymbolAddress((void**)&xh,  g_xh);  cudaGetSymbolAddress((void**)&xl,  g_xl);
    cudaGetSymbolAddress((void**)&dh,  g_dh);  cudaGetSymbolAddress((void**)&dl,  g_dl);
    cudaGetSymbolAddress((void**)&wqh, g_wqh); cudaGetSymbolAddress((void**)&wql, g_wql);
    cudaGetSymbolAddress((void**)&wkvh,g_wkvh);cudaGetSymbolAddress((void**)&wkvl,g_wkvl);
    cudaGetSymbolAddress((void**)&wph, g_wph); cudaGetSymbolAddress((void**)&wpl, g_wpl);
    cudaGetSymbolAddress((void**)&qh,  g_qh);  cudaGetSymbolAddress((void**)&ql,  g_ql);
    cudaGetSymbolAddress((void**)&kvh, g_kvh); cudaGetSymbolAddress((void**)&kvl, g_kvl);
    cudaGetSymbolAddress((void**)&ah,  g_ah);  cudaGetSymbolAddress((void**)&al,  g_al);

    cudaFuncSetAttribute(gemm_bf16x3_kernel,
                         cudaFuncAttributeMaxDynamicSharedMemorySize, GEMM_SMEM);
    cudaFuncSetAttribute(attn_hmma_kernel,
                         cudaFuncAttributeMaxDynamicSharedMemorySize, ATTN_SMEM);

    // 1. input splits & weight transposes
    split_kernel<<<(MQ * WIDTH) / 256, 256>>>(x, xh, xl, MQ * WIDTH);
    split_kernel<<<(MKV * WIDTH) / 256, 256>>>(data, dh, dl, MKV * WIDTH);
    {
        dim3 blk(32, 8);
        transpose_split_kernel<<<dim3(WIDTH / 32, WIDTH / 32), blk>>>(Wq, wqh, wql, WIDTH, WIDTH);
        transpose_split_kernel<<<dim3(NKV / 32, WIDTH / 32), blk>>>(Wkv, wkvh, wkvl, WIDTH, NKV);
        transpose_split_kernel<<<dim3(WIDTH / 32, WIDTH / 32), blk>>>(Wproj, wph, wpl, WIDTH, WIDTH);
    }

    // 2. q = x @ Wq + bq  -> split bf16 output
    gemm_bf16x3_kernel<<<dim3(WIDTH / 128, MQ / 128), 256, GEMM_SMEM>>>(
        xh, xl, wqh, wql, bq, nullptr, qh, ql, MQ, WIDTH, WIDTH);

    // 3. kv = data @ Wkv + bkv -> split bf16 output
    gemm_bf16x3_kernel<<<dim3(NKV / 128, MKV / 128), 256, GEMM_SMEM>>>(
        dh, dl, wkvh, wkvl, bkv, nullptr, kvh, kvl, MKV, NKV, WIDTH);

    // 4. attention -> split bf16 output
    attn_hmma_kernel<<<dim3(NCTX / 128, HEADS, BS), 256, ATTN_SMEM>>>();

    // 5. out = attn @ Wproj + bproj  (fp32 output)
    gemm_bf16x3_kernel<<<dim3(WIDTH / 128, MQ / 128), 256, GEMM_SMEM>>>(
        ah, al, wph, wpl, bproj, out, nullptr, nullptr, MQ, WIDTH, WIDTH);
}

// round 5
// speedup vs baseline: 3.1768x; 1.0645x over previous
#include <cuda_runtime.h>
#include <cuda_bf16.h>
#include <cstdint>

#define WIDTH 1024
#define HEADS 16
#define ACH   64
#define BS    2
#define NCTX  1024
#define NDATA 4096

#define MQ   (BS*NCTX)     // 2048
#define MKV  (BS*NDATA)    // 8192
#define NKV  (2*WIDTH)     // 2048

// ---------------- scratch (allocation-free rule: __device__ globals) --------
__device__ __nv_bfloat16 g_xh[MQ*WIDTH],   g_xl[MQ*WIDTH];
__device__ __nv_bfloat16 g_dh[MKV*WIDTH],  g_dl[MKV*WIDTH];
__device__ __nv_bfloat16 g_wqh[WIDTH*WIDTH],  g_wql[WIDTH*WIDTH];    // [N][K]
__device__ __nv_bfloat16 g_wkvh[NKV*WIDTH],   g_wkvl[NKV*WIDTH];     // [N][K]
__device__ __nv_bfloat16 g_wph[WIDTH*WIDTH],  g_wpl[WIDTH*WIDTH];    // [N][K]
__device__ __nv_bfloat16 g_qh[MQ*WIDTH],   g_ql[MQ*WIDTH];
__device__ __nv_bfloat16 g_kvh[MKV*NKV],   g_kvl[MKV*NKV];
__device__ __nv_bfloat16 g_ah[MQ*WIDTH],   g_al[MQ*WIDTH];

// ---------------- helpers -----------------------------------------------------
__device__ __forceinline__ uint32_t smem_u32(const void* p) {
    uint32_t a;
    asm("{ .reg .u64 t; cvta.to.shared.u64 t, %1; cvt.u32.u64 %0, t; }"
        : "=r"(a) : "l"(p));
    return a;
}

__device__ __forceinline__ void cp16(uint32_t dst, const void* src) {
    asm volatile("cp.async.cg.shared.global [%0], [%1], 16;" :: "r"(dst), "l"(src));
}
__device__ __forceinline__ void cp_commit() {
    asm volatile("cp.async.commit_group;" ::: "memory");
}

#define LDMATRIX_X4(r, addr)                                                    \
    asm volatile("ldmatrix.sync.aligned.m8n8.x4.shared.b16 {%0,%1,%2,%3}, [%4];" \
        : "=r"((r)[0]), "=r"((r)[1]), "=r"((r)[2]), "=r"((r)[3]) : "r"(addr))

#define LDMATRIX_X4T(r, addr)                                                   \
    asm volatile("ldmatrix.sync.aligned.m8n8.x4.trans.shared.b16 {%0,%1,%2,%3}, [%4];" \
        : "=r"((r)[0]), "=r"((r)[1]), "=r"((r)[2]), "=r"((r)[3]) : "r"(addr))

#define MMA16816(d, a, b0, b1)                                                  \
    asm volatile("mma.sync.aligned.m16n8k16.row.col.f32.bf16.bf16.f32 "         \
        "{%0,%1,%2,%3},{%4,%5,%6,%7},{%8,%9},{%0,%1,%2,%3};"                    \
        : "+f"((d)[0]), "+f"((d)[1]), "+f"((d)[2]), "+f"((d)[3])                \
        : "r"((a)[0]), "r"((a)[1]), "r"((a)[2]), "r"((a)[3]), "r"(b0), "r"(b1))

// Truncation split: hv = packed bf16 hi parts of (a,b); lv = packed bf16 of
// residuals. PRMT picks the high 16 bits of each float. Dropped mass ~2^-16.
__device__ __forceinline__ void split2(float a, float b, uint32_t& hv, uint32_t& lv) {
    uint32_t ia = __float_as_uint(a);
    uint32_t ib = __float_as_uint(b);
    asm("prmt.b32 %0, %1, %2, 0x7632;" : "=r"(hv) : "r"(ia), "r"(ib));
    float ra = a - __uint_as_float(ia & 0xFFFF0000u);
    float rb = b - __uint_as_float(ib & 0xFFFF0000u);
    uint32_t ira = __float_as_uint(ra);
    uint32_t irb = __float_as_uint(rb);
    asm("prmt.b32 %0, %1, %2, 0x7632;" : "=r"(lv) : "r"(ira), "r"(irb));
}

// ---------------- conversion kernels ----------------------------------------
__global__ void split_kernel(const float* __restrict__ src,
                             __nv_bfloat16* __restrict__ h,
                             __nv_bfloat16* __restrict__ l, int n)
{
    int i = blockIdx.x * blockDim.x + threadIdx.x;
    if (i < n) {
        float x = src[i];
        __nv_bfloat16 hh = __float2bfloat16(x);
        h[i] = hh;
        l[i] = __float2bfloat16(x - __bfloat162float(hh));
    }
}

// W [Kdim][Ndim] fp32 -> Th/Tl [Ndim][Kdim] bf16
__global__ void transpose_split_kernel(const float* __restrict__ W,
                                       __nv_bfloat16* __restrict__ Th,
                                       __nv_bfloat16* __restrict__ Tl,
                                       int Kdim, int Ndim)
{
    __shared__ float tile[32][33];
    int tx = threadIdx.x, ty = threadIdx.y;
    int n0 = blockIdx.x * 32;
    int k0 = blockIdx.y * 32;
#pragma unroll
    for (int i = 0; i < 4; i++) {
        int k = k0 + ty + i * 8;
        tile[ty + i * 8][tx] = W[(size_t)k * Ndim + n0 + tx];
    }
    __syncthreads();
#pragma unroll
    for (int i = 0; i < 4; i++) {
        int n = n0 + ty + i * 8;
        int k = k0 + tx;
        float v = tile[tx][ty + i * 8];
        __nv_bfloat16 hh = __float2bfloat16(v);
        Th[(size_t)n * Kdim + k] = hh;
        Tl[(size_t)n * Kdim + k] = __float2bfloat16(v - __bfloat162float(hh));
    }
}

// ---------------- bf16x3 HMMA GEMM --------------------------------------------
// C = (Ah+Al)[M,K] @ (Bh+Bl)[N,K]^T + bias, fp32 acc.
// 4-stage ring, prefetch depth 2, ONE syncthreads per k-chunk.
#define ROWB    80
#define TILE_B  (128*ROWB)
#define OFF_AH  0
#define OFF_AL  TILE_B
#define OFF_BH  (2*TILE_B)
#define OFF_BL  (3*TILE_B)
#define STAGE_B (4*TILE_B)          // 40960
#define NSTAGE  4
#define GEMM_SMEM (NSTAGE*STAGE_B)  // 163840

__device__ __forceinline__ void load_stage(
    uint32_t base,
    const __nv_bfloat16* __restrict__ Ah, const __nv_bfloat16* __restrict__ Al,
    const __nv_bfloat16* __restrict__ Bh, const __nv_bfloat16* __restrict__ Bl,
    int K, int bm, int bn, int kc, int tid)
{
    int k0 = kc * 32;
#pragma unroll
    for (int i = 0; i < 2; i++) {
        int idx = tid + i * 256;
        int row = idx >> 2;
        int seg = idx & 3;
        uint32_t off = (uint32_t)(row * ROWB + seg * 16);
        size_t gea = (size_t)(bm + row) * K + k0 + seg * 8;
        size_t geb = (size_t)(bn + row) * K + k0 + seg * 8;
        cp16(base + OFF_AH + off, Ah + gea);
        cp16(base + OFF_AL + off, Al + gea);
        cp16(base + OFF_BH + off, Bh + geb);
        cp16(base + OFF_BL + off, Bl + geb);
    }
}

__global__ void __launch_bounds__(256)
gemm_bf16x3_kernel(const __nv_bfloat16* __restrict__ Ah, const __nv_bfloat16* __restrict__ Al,
                   const __nv_bfloat16* __restrict__ Bh, const __nv_bfloat16* __restrict__ Bl,
                   const float* __restrict__ bias,
                   float* __restrict__ C,
                   __nv_bfloat16* __restrict__ Ch, __nv_bfloat16* __restrict__ Cl,
                   int M, int N, int K)
{
    extern __shared__ char smem[];
    const uint32_t sb = smem_u32(smem);

    const int tid  = threadIdx.x;
    const int lane = tid & 31;
    const int wid  = tid >> 5;
    const int warp_m = wid & 3;
    const int warp_n = wid >> 2;
    const int bm = blockIdx.y * 128;
    const int bn = blockIdx.x * 128;

    const uint32_t a_byte = (uint32_t)((warp_m * 32 + (lane & 15)) * ROWB + ((lane >> 4) << 4));
    const uint32_t b_byte = (uint32_t)((warp_n * 64 + (lane & 7) + ((lane >> 4) << 3)) * ROWB
                                       + (((lane >> 3) & 1) << 4));

    float acc[2][8][4];
#pragma unroll
    for (int mi = 0; mi < 2; mi++)
#pragma unroll
        for (int j = 0; j < 8; j++)
#pragma unroll
            for (int r = 0; r < 4; r++) acc[mi][j][r] = 0.0f;

    const int nchunk = K >> 5;

    // prologue: prefetch chunks 0,1
    load_stage(sb, Ah, Al, Bh, Bl, K, bm, bn, 0, tid);
    cp_commit();
    load_stage(sb + STAGE_B, Ah, Al, Bh, Bl, K, bm, bn, 1, tid);
    cp_commit();

    for (int kc = 0; kc < nchunk; kc++) {
        asm volatile("cp.async.wait_group 1;" ::: "memory");
        __syncthreads();

        // early prefetch into slot (kc+2)%4 — nobody touches it (readers were
        // at kc-2, two syncthreads back)
        if (kc + 2 < nchunk) {
            load_stage(sb + (uint32_t)((kc + 2) & 3) * STAGE_B,
                       Ah, Al, Bh, Bl, K, bm, bn, kc + 2, tid);
            cp_commit();
        }

        uint32_t sbase = sb + (uint32_t)(kc & 3) * STAGE_B;

#pragma unroll
        for (int ks = 0; ks < 2; ks++) {
            uint32_t kofs = (uint32_t)(ks * 32);
            uint32_t ahr[2][4], alr[2][4];
#pragma unroll
            for (int mi = 0; mi < 2; mi++) {
                uint32_t ao = a_byte + (uint32_t)(mi * 16 * ROWB) + kofs;
                LDMATRIX_X4(ahr[mi], sbase + OFF_AH + ao);
                LDMATRIX_X4(alr[mi], sbase + OFF_AL + ao);
            }
#pragma unroll
            for (int ni = 0; ni < 4; ni++) {
                uint32_t bo = b_byte + (uint32_t)(ni * 16 * ROWB) + kofs;
                uint32_t bhr[4], blr[4];
                LDMATRIX_X4(bhr, sbase + OFF_BH + bo);
                LDMATRIX_X4(blr, sbase + OFF_BL + bo);
#pragma unroll
                for (int mi = 0; mi < 2; mi++) {
                    MMA16816(acc[mi][2 * ni],     ahr[mi], bhr[0], bhr[1]);
                    MMA16816(acc[mi][2 * ni + 1], ahr[mi], bhr[2], bhr[3]);
                    MMA16816(acc[mi][2 * ni],     ahr[mi], blr[0], blr[1]);
                    MMA16816(acc[mi][2 * ni + 1], ahr[mi], blr[2], blr[3]);
                    MMA16816(acc[mi][2 * ni],     alr[mi], bhr[0], bhr[1]);
                    MMA16816(acc[mi][2 * ni + 1], alr[mi], bhr[2], bhr[3]);
                }
            }
        }
    }

    const int m_base = bm + warp_m * 32;
    const int n_base = bn + warp_n * 64;
    const int rq = lane >> 2;
    const int cq = (lane & 3) * 2;
#pragma unroll
    for (int mi = 0; mi < 2; mi++) {
#pragma unroll
        for (int j = 0; j < 8; j++) {
            int col = n_base + j * 8 + cq;
            float b0 = bias[col];
            float b1 = bias[col + 1];
            int r0 = m_base + mi * 16 + rq;
            float v0 = acc[mi][j][0] + b0, v1 = acc[mi][j][1] + b1;
            float v2 = acc[mi][j][2] + b0, v3 = acc[mi][j][3] + b1;
            if (Ch) {
                uint32_t hv, lv;
                split2(v0, v1, hv, lv);
                *(uint32_t*)&Ch[(size_t)r0 * N + col] = hv;
                *(uint32_t*)&Cl[(size_t)r0 * N + col] = lv;
                split2(v2, v3, hv, lv);
                *(uint32_t*)&Ch[(size_t)(r0 + 8) * N + col] = hv;
                *(uint32_t*)&Cl[(size_t)(r0 + 8) * N + col] = lv;
            } else {
                *(float2*)&C[(size_t)r0 * N + col]       = make_float2(v0, v1);
                *(float2*)&C[(size_t)(r0 + 8) * N + col] = make_float2(v2, v3);
            }
        }
    }
}

// ---------------- HMMA flash attention ----------------------------------------
// 128 query rows per CTA for one (b,h). 8 warps x m16. bf16x3 QK^T and PV.
// 4-stage KV ring, prefetch depth 2, ONE syncthreads per chunk.
#define APITCH 144
#define AQH 0
#define AQL (128*APITCH)                 // 18432
#define AST (2*128*APITCH)               // 36864  (Q region size)
#define TKH 0
#define TKL (64*APITCH)                  // 9216
#define TVH (128*APITCH)
#define TVL (192*APITCH)
#define ASTAGE (256*APITCH)              // 36864
#define ANSTAGE 4
#define ATTN_SMEM (AST + ANSTAGE*ASTAGE) // 184320

__device__ __forceinline__ void load_kv_stage(uint32_t dst, int b, int h, int s0, int tid)
{
#pragma unroll
    for (int i = 0; i < 2; i++) {
        int idx = tid + i * 256;
        int row = idx >> 3;
        int seg = idx & 7;
        size_t base = (size_t)(b * NDATA + s0 + row) * NKV + h * 128 + seg * 8;
        uint32_t so = (uint32_t)(row * APITCH + seg * 16);
        cp16(dst + TKH + so, g_kvh + base);
        cp16(dst + TKL + so, g_kvl + base);
        cp16(dst + TVH + so, g_kvh + base + 64);
        cp16(dst + TVL + so, g_kvl + base + 64);
    }
}

__global__ void __launch_bounds__(256)
attn_hmma_kernel()
{
    extern __shared__ char smem[];
    const uint32_t sb = smem_u32(smem);

    const int tid  = threadIdx.x;
    const int lane = tid & 31;
    const int wid  = tid >> 5;
    const int qt = blockIdx.x;
    const int h  = blockIdx.y;
    const int b  = blockIdx.z;
    const int t0 = qt * 128;

    // group 1: Q tile
#pragma unroll
    for (int i = 0; i < 4; i++) {
        int idx = tid + i * 256;
        int row = idx >> 3;
        int seg = idx & 7;
        size_t go = (size_t)(b * NCTX + t0 + row) * WIDTH + h * ACH + seg * 8;
        uint32_t so = (uint32_t)(row * APITCH + seg * 16);
        cp16(sb + AQH + so, g_qh + go);
        cp16(sb + AQL + so, g_ql + go);
    }
    cp_commit();
    // groups 2,3: KV chunks 0,1
    load_kv_stage(sb + AST, b, h, 0, tid);
    cp_commit();
    load_kv_stage(sb + AST + ASTAGE, b, h, 64, tid);
    cp_commit();

    // Q fragments (registers for whole kernel); wait for group 1 only
    asm volatile("cp.async.wait_group 2;" ::: "memory");
    __syncthreads();
    uint32_t qhf[4][4], qlf[4][4];
    {
        uint32_t qa = (uint32_t)((wid * 16 + (lane & 15)) * APITCH + ((lane >> 4) << 4));
#pragma unroll
        for (int kc = 0; kc < 4; kc++) {
            LDMATRIX_X4(qhf[kc], sb + AQH + qa + kc * 32);
            LDMATRIX_X4(qlf[kc], sb + AQL + qa + kc * 32);
        }
    }

    const uint32_t kb = (uint32_t)(((lane & 7) + ((lane >> 4) << 3)) * APITCH
                                   + (((lane >> 3) & 1) << 4));
    const uint32_t vb = (uint32_t)((lane & 15) * APITCH + ((lane >> 4) << 4));

    float m2[2] = {-1e30f, -1e30f};
    float l[2]  = {0.0f, 0.0f};
    float o[8][4];
#pragma unroll
    for (int j = 0; j < 8; j++)
#pragma unroll
        for (int e = 0; e < 4; e++) o[j][e] = 0.0f;

    const float CS = 0.125f * 1.44269504f;

    const int NCHUNK = NDATA / 64;    // 64
    for (int sc = 0; sc < NCHUNK; sc++) {
        asm volatile("cp.async.wait_group 1;" ::: "memory");
        __syncthreads();

        // early prefetch into ring slot (sc+2)%4
        if (sc + 2 < NCHUNK) {
            load_kv_stage(sb + AST + (uint32_t)((sc + 2) & 3) * ASTAGE,
                          b, h, (sc + 2) * 64, tid);
            cp_commit();
        }

        uint32_t st = sb + AST + (uint32_t)(sc & 3) * ASTAGE;

        // ---- S = Q K^T (bf16x3) ----
        float sacc[8][4];
#pragma unroll
        for (int j = 0; j < 8; j++)
#pragma unroll
            for (int e = 0; e < 4; e++) sacc[j][e] = 0.0f;

#pragma unroll
        for (int kc = 0; kc < 4; kc++) {
#pragma unroll
            for (int g = 0; g < 4; g++) {
                uint32_t ko = kb + (uint32_t)(g * 16 * APITCH) + kc * 32;
                uint32_t khf[4], klf[4];
                LDMATRIX_X4(khf, st + TKH + ko);
                LDMATRIX_X4(klf, st + TKL + ko);
                MMA16816(sacc[2 * g],     qhf[kc], khf[0], khf[1]);
                MMA16816(sacc[2 * g + 1], qhf[kc], khf[2], khf[3]);
                MMA16816(sacc[2 * g],     qhf[kc], klf[0], klf[1]);
                MMA16816(sacc[2 * g + 1], qhf[kc], klf[2], klf[3]);
                MMA16816(sacc[2 * g],     qlf[kc], khf[0], khf[1]);
                MMA16816(sacc[2 * g + 1], qlf[kc], khf[2], khf[3]);
            }
        }

        // ---- online softmax (base-2, scale folded) ----
        float mx0 = -1e30f, mx1 = -1e30f;
#pragma unroll
        for (int j = 0; j < 8; j++) {
            mx0 = fmaxf(mx0, fmaxf(sacc[j][0], sacc[j][1]));
            mx1 = fmaxf(mx1, fmaxf(sacc[j][2], sacc[j][3]));
        }
        mx0 *= CS; mx1 *= CS;
        mx0 = fmaxf(mx0, __shfl_xor_sync(0xffffffffu, mx0, 1));
        mx0 = fmaxf(mx0, __shfl_xor_sync(0xffffffffu, mx0, 2));
        mx1 = fmaxf(mx1, __shfl_xor_sync(0xffffffffu, mx1, 1));
        mx1 = fmaxf(mx1, __shfl_xor_sync(0xffffffffu, mx1, 2));
        float mn0 = fmaxf(m2[0], mx0), mn1 = fmaxf(m2[1], mx1);
        float c0 = exp2f(m2[0] - mn0), c1 = exp2f(m2[1] - mn1);
        m2[0] = mn0; m2[1] = mn1;

        float rs0 = 0.0f, rs1 = 0.0f;
#pragma unroll
        for (int j = 0; j < 8; j++) {
            float p0 = exp2f(fmaf(sacc[j][0], CS, -mn0));
            float p1 = exp2f(fmaf(sacc[j][1], CS, -mn0));
            float p2 = exp2f(fmaf(sacc[j][2], CS, -mn1));
            float p3 = exp2f(fmaf(sacc[j][3], CS, -mn1));
            sacc[j][0] = p0; sacc[j][1] = p1; sacc[j][2] = p2; sacc[j][3] = p3;
            rs0 += p0 + p1; rs1 += p2 + p3;
        }
        rs0 += __shfl_xor_sync(0xffffffffu, rs0, 1);
        rs0 += __shfl_xor_sync(0xffffffffu, rs0, 2);
        rs1 += __shfl_xor_sync(0xffffffffu, rs1, 1);
        rs1 += __shfl_xor_sync(0xffffffffu, rs1, 2);
        l[0] = l[0] * c0 + rs0;
        l[1] = l[1] * c1 + rs1;
#pragma unroll
        for (int j = 0; j < 8; j++) {
            o[j][0] *= c0; o[j][1] *= c0;
            o[j][2] *= c1; o[j][3] *= c1;
        }

        // ---- pack P into A fragments ----
        uint32_t ph[4][4], pl[4][4];
#pragma unroll
        for (int kc = 0; kc < 4; kc++) {
            int j0 = 2 * kc, j1 = 2 * kc + 1;
            split2(sacc[j0][0], sacc[j0][1], ph[kc][0], pl[kc][0]);
            split2(sacc[j0][2], sacc[j0][3], ph[kc][1], pl[kc][1]);
            split2(sacc[j1][0], sacc[j1][1], ph[kc][2], pl[kc][2]);
            split2(sacc[j1][2], sacc[j1][3], ph[kc][3], pl[kc][3]);
        }

        // ---- O += P V (bf16x3) ----
#pragma unroll
        for (int kc = 0; kc < 4; kc++) {
#pragma unroll
            for (int g = 0; g < 4; g++) {
                uint32_t vo = vb + (uint32_t)(kc * 16 * APITCH) + g * 32;
                uint32_t vhf[4], vlf[4];
                LDMATRIX_X4T(vhf, st + TVH + vo);
                LDMATRIX_X4T(vlf, st + TVL + vo);
                MMA16816(o[2 * g],     ph[kc], vhf[0], vhf[1]);
                MMA16816(o[2 * g + 1], ph[kc], vhf[2], vhf[3]);
                MMA16816(o[2 * g],     ph[kc], vlf[0], vlf[1]);
                MMA16816(o[2 * g + 1], ph[kc], vlf[2], vlf[3]);
                MMA16816(o[2 * g],     pl[kc], vhf[0], vhf[1]);
                MMA16816(o[2 * g + 1], pl[kc], vhf[2], vhf[3]);
            }
        }
    }

    // ---- epilogue: normalize, split, store ----
    float inv0 = 1.0f / l[0];
    float inv1 = 1.0f / l[1];
    int r = t0 + wid * 16 + (lane >> 2);
    int cq = (lane & 3) * 2;
#pragma unroll
    for (int j = 0; j < 8; j++) {
        int col = h * ACH + j * 8 + cq;
        uint32_t hv, lv;
        split2(o[j][0] * inv0, o[j][1] * inv0, hv, lv);
        *(uint32_t*)&g_ah[(size_t)(b * NCTX + r) * WIDTH + col] = hv;
        *(uint32_t*)&g_al[(size_t)(b * NCTX + r) * WIDTH + col] = lv;
        split2(o[j][2] * inv1, o[j][3] * inv1, hv, lv);
        *(uint32_t*)&g_ah[(size_t)(b * NCTX + r + 8) * WIDTH + col] = hv;
        *(uint32_t*)&g_al[(size_t)(b * NCTX + r + 8) * WIDTH + col] = lv;
    }
}

// ---------------- launch ------------------------------------------------------
extern "C" void kernel_launch(void* const* d_in, const int* in_sizes, int n_in,
                              void* d_out, int out_size)
{
    (void)in_sizes; (void)n_in; (void)out_size;

    const float* x     = (const float*)d_in[0];
    const float* data  = (const float*)d_in[1];
    const float* Wq    = (const float*)d_in[2];
    const float* bq    = (const float*)d_in[3];
    const float* Wkv   = (const float*)d_in[4];
    const float* bkv   = (const float*)d_in[5];
    const float* Wproj = (const float*)d_in[6];
    const float* bproj = (const float*)d_in[7];
    float* out = (float*)d_out;

    __nv_bfloat16 *xh, *xl, *dh, *dl, *wqh, *wql, *wkvh, *wkvl, *wph, *wpl;
    __nv_bfloat16 *qh, *ql, *kvh, *kvl, *ah, *al;
    cudaGetSymbolAddress((void**)&xh,  g_xh);  cudaGetSymbolAddress((void**)&xl,  g_xl);
    cudaGetSymbolAddress((void**)&dh,  g_dh);  cudaGetSymbolAddress((void**)&dl,  g_dl);
    cudaGetSymbolAddress((void**)&wqh, g_wqh); cudaGetSymbolAddress((void**)&wql, g_wql);
    cudaGetSymbolAddress((void**)&wkvh,g_wkvh);cudaGetSymbolAddress((void**)&wkvl,g_wkvl);
    cudaGetSymbolAddress((void**)&wph, g_wph); cudaGetSymbolAddress((void**)&wpl, g_wpl);
    cudaGetSymbolAddress((void**)&qh,  g_qh);  cudaGetSymbolAddress((void**)&ql,  g_ql);
    cudaGetSymbolAddress((void**)&kvh, g_kvh); cudaGetSymbolAddress((void**)&kvl, g_kvl);
    cudaGetSymbolAddress((void**)&ah,  g_ah);  cudaGetSymbolAddress((void**)&al,  g_al);

    cudaFuncSetAttribute(gemm_bf16x3_kernel,
                         cudaFuncAttributeMaxDynamicSharedMemorySize, GEMM_SMEM);
    cudaFuncSetAttribute(attn_hmma_kernel,
                         cudaFuncAttributeMaxDynamicSharedMemorySize, ATTN_SMEM);

    // 1. input splits & weight transposes
    split_kernel<<<(MQ * WIDTH) / 256, 256>>>(x, xh, xl, MQ * WIDTH);
    split_kernel<<<(MKV * WIDTH) / 256, 256>>>(data, dh, dl, MKV * WIDTH);
    {
        dim3 blk(32, 8);
        transpose_split_kernel<<<dim3(WIDTH / 32, WIDTH / 32), blk>>>(Wq, wqh, wql, WIDTH, WIDTH);
        transpose_split_kernel<<<dim3(NKV / 32, WIDTH / 32), blk>>>(Wkv, wkvh, wkvl, WIDTH, NKV);
        transpose_split_kernel<<<dim3(WIDTH / 32, WIDTH / 32), blk>>>(Wproj, wph, wpl, WIDTH, WIDTH);
    }

    // 2. q = x @ Wq + bq  -> split bf16 output
    gemm_bf16x3_kernel<<<dim3(WIDTH / 128, MQ / 128), 256, GEMM_SMEM>>>(
        xh, xl, wqh, wql, bq, nullptr, qh, ql, MQ, WIDTH, WIDTH);

    // 3. kv = data @ Wkv + bkv -> split bf16 output
    gemm_bf16x3_kernel<<<dim3(NKV / 128, MKV / 128), 256, GEMM_SMEM>>>(
        dh, dl, wkvh, wkvl, bkv, nullptr, kvh, kvl, MKV, NKV, WIDTH);

    // 4. attention -> split bf16 output
    attn_hmma_kernel<<<dim3(NCTX / 128, HEADS, BS), 256, ATTN_SMEM>>>();

    // 5. out = attn @ Wproj + bproj  (fp32 output)
    gemm_bf16x3_kernel<<<dim3(WIDTH / 128, MQ / 128), 256, GEMM_SMEM>>>(
        ah, al, wph, wpl, bproj, out, nullptr, nullptr, MQ, WIDTH, WIDTH);
}

// round 6
// speedup vs baseline: 3.6217x; 1.1400x over previous
#include <cuda_runtime.h>
#include <cuda_bf16.h>
#include <cstdint>

#define WIDTH 1024
#define HEADS 16
#define ACH   64
#define BS    2
#define NCTX  1024
#define NDATA 4096

#define MQ   (BS*NCTX)     // 2048
#define MKV  (BS*NDATA)    // 8192
#define NKV  (2*WIDTH)     // 2048

// ---------------- scratch (allocation-free rule: __device__ globals) --------
__device__ __nv_bfloat16 g_xh[MQ*WIDTH],   g_xl[MQ*WIDTH];
__device__ __nv_bfloat16 g_dh[MKV*WIDTH],  g_dl[MKV*WIDTH];
__device__ __nv_bfloat16 g_wqh[WIDTH*WIDTH],  g_wql[WIDTH*WIDTH];    // [N][K]
__device__ __nv_bfloat16 g_wkvh[NKV*WIDTH],   g_wkvl[NKV*WIDTH];     // [N][K]
__device__ __nv_bfloat16 g_wph[WIDTH*WIDTH],  g_wpl[WIDTH*WIDTH];    // [N][K]
__device__ __nv_bfloat16 g_qh[MQ*WIDTH];
__device__ __nv_bfloat16 g_ql[MQ*WIDTH];       // unused (kept for call symmetry)
__device__ __nv_bfloat16 g_kvh[MKV*NKV],   g_kvl[MKV*NKV];
__device__ __nv_bfloat16 g_ah[MQ*WIDTH],   g_al[MQ*WIDTH];

// ---------------- helpers -----------------------------------------------------
__device__ __forceinline__ uint32_t smem_u32(const void* p) {
    uint32_t a;
    asm("{ .reg .u64 t; cvta.to.shared.u64 t, %1; cvt.u32.u64 %0, t; }"
        : "=r"(a) : "l"(p));
    return a;
}

__device__ __forceinline__ void cp16(uint32_t dst, const void* src) {
    asm volatile("cp.async.cg.shared.global [%0], [%1], 16;" :: "r"(dst), "l"(src));
}
__device__ __forceinline__ void cp_commit() {
    asm volatile("cp.async.commit_group;" ::: "memory");
}

#define LDMATRIX_X4(r, addr)                                                    \
    asm volatile("ldmatrix.sync.aligned.m8n8.x4.shared.b16 {%0,%1,%2,%3}, [%4];" \
        : "=r"((r)[0]), "=r"((r)[1]), "=r"((r)[2]), "=r"((r)[3]) : "r"(addr))

#define LDMATRIX_X4T(r, addr)                                                   \
    asm volatile("ldmatrix.sync.aligned.m8n8.x4.trans.shared.b16 {%0,%1,%2,%3}, [%4];" \
        : "=r"((r)[0]), "=r"((r)[1]), "=r"((r)[2]), "=r"((r)[3]) : "r"(addr))

#define MMA16816(d, a, b0, b1)                                                  \
    asm volatile("mma.sync.aligned.m16n8k16.row.col.f32.bf16.bf16.f32 "         \
        "{%0,%1,%2,%3},{%4,%5,%6,%7},{%8,%9},{%0,%1,%2,%3};"                    \
        : "+f"((d)[0]), "+f"((d)[1]), "+f"((d)[2]), "+f"((d)[3])                \
        : "r"((a)[0]), "r"((a)[1]), "r"((a)[2]), "r"((a)[3]), "r"(b0), "r"(b1))

// Truncation split via PRMT (no cvt chain); dropped mass ~2^-16.
__device__ __forceinline__ void split2(float a, float b, uint32_t& hv, uint32_t& lv) {
    uint32_t ia = __float_as_uint(a);
    uint32_t ib = __float_as_uint(b);
    asm("prmt.b32 %0, %1, %2, 0x7632;" : "=r"(hv) : "r"(ia), "r"(ib));
    float ra = a - __uint_as_float(ia & 0xFFFF0000u);
    float rb = b - __uint_as_float(ib & 0xFFFF0000u);
    uint32_t ira = __float_as_uint(ra);
    uint32_t irb = __float_as_uint(rb);
    asm("prmt.b32 %0, %1, %2, 0x7632;" : "=r"(lv) : "r"(ira), "r"(irb));
}

__device__ __forceinline__ uint32_t pack_hi2(float a, float b) {
    uint32_t hv;
    asm("prmt.b32 %0, %1, %2, 0x7632;" : "=r"(hv) : "r"(__float_as_uint(a)), "r"(__float_as_uint(b)));
    return hv;
}

// ---------------- conversion kernels ----------------------------------------
__global__ void split_kernel(const float* __restrict__ src,
                             __nv_bfloat16* __restrict__ h,
                             __nv_bfloat16* __restrict__ l, int n)
{
    int i = blockIdx.x * blockDim.x + threadIdx.x;
    if (i < n) {
        float x = src[i];
        __nv_bfloat16 hh = __float2bfloat16(x);
        h[i] = hh;
        l[i] = __float2bfloat16(x - __bfloat162float(hh));
    }
}

// W [Kdim][Ndim] fp32 -> Th/Tl [Ndim][Kdim] bf16
__global__ void transpose_split_kernel(const float* __restrict__ W,
                                       __nv_bfloat16* __restrict__ Th,
                                       __nv_bfloat16* __restrict__ Tl,
                                       int Kdim, int Ndim)
{
    __shared__ float tile[32][33];
    int tx = threadIdx.x, ty = threadIdx.y;
    int n0 = blockIdx.x * 32;
    int k0 = blockIdx.y * 32;
#pragma unroll
    for (int i = 0; i < 4; i++) {
        int k = k0 + ty + i * 8;
        tile[ty + i * 8][tx] = W[(size_t)k * Ndim + n0 + tx];
    }
    __syncthreads();
#pragma unroll
    for (int i = 0; i < 4; i++) {
        int n = n0 + ty + i * 8;
        int k = k0 + tx;
        float v = tile[tx][ty + i * 8];
        __nv_bfloat16 hh = __float2bfloat16(v);
        Th[(size_t)n * Kdim + k] = hh;
        Tl[(size_t)n * Kdim + k] = __float2bfloat16(v - __bfloat162float(hh));
    }
}

// ---------------- bf16x3 HMMA GEMM --------------------------------------------
// C = (Ah+Al)[M,K] @ (Bh+Bl)[N,K]^T + bias, fp32 acc.
// mode 0: fp32 C. mode 1: split bf16 (h,l). mode 2: bf16 h only.
// mode 3: kv layout — warp_n==0 (K half): h only; warp_n==1 (V half): h+l.
#define ROWB    80
#define TILE_B  (128*ROWB)
#define OFF_AH  0
#define OFF_AL  TILE_B
#define OFF_BH  (2*TILE_B)
#define OFF_BL  (3*TILE_B)
#define STAGE_B (4*TILE_B)          // 40960
#define NSTAGE  4
#define GEMM_SMEM (NSTAGE*STAGE_B)  // 163840

__device__ __forceinline__ void load_stage(
    uint32_t base,
    const __nv_bfloat16* __restrict__ Ah, const __nv_bfloat16* __restrict__ Al,
    const __nv_bfloat16* __restrict__ Bh, const __nv_bfloat16* __restrict__ Bl,
    int K, int bm, int bn, int kc, int tid)
{
    int k0 = kc * 32;
#pragma unroll
    for (int i = 0; i < 2; i++) {
        int idx = tid + i * 256;
        int row = idx >> 2;
        int seg = idx & 3;
        uint32_t off = (uint32_t)(row * ROWB + seg * 16);
        size_t gea = (size_t)(bm + row) * K + k0 + seg * 8;
        size_t geb = (size_t)(bn + row) * K + k0 + seg * 8;
        cp16(base + OFF_AH + off, Ah + gea);
        cp16(base + OFF_AL + off, Al + gea);
        cp16(base + OFF_BH + off, Bh + geb);
        cp16(base + OFF_BL + off, Bl + geb);
    }
}

__global__ void __launch_bounds__(256)
gemm_bf16x3_kernel(const __nv_bfloat16* __restrict__ Ah, const __nv_bfloat16* __restrict__ Al,
                   const __nv_bfloat16* __restrict__ Bh, const __nv_bfloat16* __restrict__ Bl,
                   const float* __restrict__ bias,
                   float* __restrict__ C,
                   __nv_bfloat16* __restrict__ Ch, __nv_bfloat16* __restrict__ Cl,
                   int M, int N, int K, int mode)
{
    extern __shared__ char smem[];
    const uint32_t sb = smem_u32(smem);

    const int tid  = threadIdx.x;
    const int lane = tid & 31;
    const int wid  = tid >> 5;
    const int warp_m = wid & 3;
    const int warp_n = wid >> 2;
    const int bm = blockIdx.y * 128;
    const int bn = blockIdx.x * 128;

    const uint32_t a_byte = (uint32_t)((warp_m * 32 + (lane & 15)) * ROWB + ((lane >> 4) << 4));
    const uint32_t b_byte = (uint32_t)((warp_n * 64 + (lane & 7) + ((lane >> 4) << 3)) * ROWB
                                       + (((lane >> 3) & 1) << 4));

    float acc[2][8][4];
#pragma unroll
    for (int mi = 0; mi < 2; mi++)
#pragma unroll
        for (int j = 0; j < 8; j++)
#pragma unroll
            for (int r = 0; r < 4; r++) acc[mi][j][r] = 0.0f;

    const int nchunk = K >> 5;

    load_stage(sb, Ah, Al, Bh, Bl, K, bm, bn, 0, tid);
    cp_commit();
    load_stage(sb + STAGE_B, Ah, Al, Bh, Bl, K, bm, bn, 1, tid);
    cp_commit();

    for (int kc = 0; kc < nchunk; kc++) {
        asm volatile("cp.async.wait_group 1;" ::: "memory");
        __syncthreads();

        if (kc + 2 < nchunk) {
            load_stage(sb + (uint32_t)((kc + 2) & 3) * STAGE_B,
                       Ah, Al, Bh, Bl, K, bm, bn, kc + 2, tid);
            cp_commit();
        }

        uint32_t sbase = sb + (uint32_t)(kc & 3) * STAGE_B;

#pragma unroll
        for (int ks = 0; ks < 2; ks++) {
            uint32_t kofs = (uint32_t)(ks * 32);
            uint32_t ahr[2][4], alr[2][4];
#pragma unroll
            for (int mi = 0; mi < 2; mi++) {
                uint32_t ao = a_byte + (uint32_t)(mi * 16 * ROWB) + kofs;
                LDMATRIX_X4(ahr[mi], sbase + OFF_AH + ao);
                LDMATRIX_X4(alr[mi], sbase + OFF_AL + ao);
            }
#pragma unroll
            for (int ni = 0; ni < 4; ni++) {
                uint32_t bo = b_byte + (uint32_t)(ni * 16 * ROWB) + kofs;
                uint32_t bhr[4], blr[4];
                LDMATRIX_X4(bhr, sbase + OFF_BH + bo);
                LDMATRIX_X4(blr, sbase + OFF_BL + bo);
#pragma unroll
                for (int mi = 0; mi < 2; mi++) {
                    MMA16816(acc[mi][2 * ni],     ahr[mi], bhr[0], bhr[1]);
                    MMA16816(acc[mi][2 * ni + 1], ahr[mi], bhr[2], bhr[3]);
                    MMA16816(acc[mi][2 * ni],     ahr[mi], blr[0], blr[1]);
                    MMA16816(acc[mi][2 * ni + 1], ahr[mi], blr[2], blr[3]);
                    MMA16816(acc[mi][2 * ni],     alr[mi], bhr[0], bhr[1]);
                    MMA16816(acc[mi][2 * ni + 1], alr[mi], bhr[2], bhr[3]);
                }
            }
        }
    }

    const int m_base = bm + warp_m * 32;
    const int n_base = bn + warp_n * 64;
    const int rq = lane >> 2;
    const int cq = (lane & 3) * 2;
    const bool store_lo = (mode == 1) || (mode == 3 && warp_n == 1);
#pragma unroll
    for (int mi = 0; mi < 2; mi++) {
#pragma unroll
        for (int j = 0; j < 8; j++) {
            int col = n_base + j * 8 + cq;
            float b0 = bias[col];
            float b1 = bias[col + 1];
            int r0 = m_base + mi * 16 + rq;
            float v0 = acc[mi][j][0] + b0, v1 = acc[mi][j][1] + b1;
            float v2 = acc[mi][j][2] + b0, v3 = acc[mi][j][3] + b1;
            if (mode == 0) {
                *(float2*)&C[(size_t)r0 * N + col]       = make_float2(v0, v1);
                *(float2*)&C[(size_t)(r0 + 8) * N + col] = make_float2(v2, v3);
            } else if (store_lo) {
                uint32_t hv, lv;
                split2(v0, v1, hv, lv);
                *(uint32_t*)&Ch[(size_t)r0 * N + col] = hv;
                *(uint32_t*)&Cl[(size_t)r0 * N + col] = lv;
                split2(v2, v3, hv, lv);
                *(uint32_t*)&Ch[(size_t)(r0 + 8) * N + col] = hv;
                *(uint32_t*)&Cl[(size_t)(r0 + 8) * N + col] = lv;
            } else {
                *(uint32_t*)&Ch[(size_t)r0 * N + col]       = pack_hi2(v0, v1);
                *(uint32_t*)&Ch[(size_t)(r0 + 8) * N + col] = pack_hi2(v2, v3);
            }
        }
    }
}

// ---------------- HMMA flash attention ----------------------------------------
// 128 query rows per CTA for one (b,h). 8 warps x m16.
// QK^T: pure bf16 (Qh*Kh). PV: bf16x3. 4-stage KV ring, 1 sync per chunk.
#define APITCH 144
#define AQH 0
#define AST (128*APITCH)                 // 18432 (Q region: h only)
#define TKH 0
#define TVH (64*APITCH)                  // 9216
#define TVL (128*APITCH)                 // 18432
#define ASTAGE (192*APITCH)              // 27648
#define ANSTAGE 4
#define ATTN_SMEM (AST + ANSTAGE*ASTAGE) // 129024

__device__ __forceinline__ void load_kv_stage(uint32_t dst, int b, int h, int s0, int tid)
{
#pragma unroll
    for (int i = 0; i < 2; i++) {
        int idx = tid + i * 256;
        int row = idx >> 3;
        int seg = idx & 7;
        size_t base = (size_t)(b * NDATA + s0 + row) * NKV + h * 128 + seg * 8;
        uint32_t so = (uint32_t)(row * APITCH + seg * 16);
        cp16(dst + TKH + so, g_kvh + base);          // K hi
        cp16(dst + TVH + so, g_kvh + base + 64);     // V hi
        cp16(dst + TVL + so, g_kvl + base + 64);     // V lo
    }
}

__global__ void __launch_bounds__(256)
attn_hmma_kernel()
{
    extern __shared__ char smem[];
    const uint32_t sb = smem_u32(smem);

    const int tid  = threadIdx.x;
    const int lane = tid & 31;
    const int wid  = tid >> 5;
    const int qt = blockIdx.x;
    const int h  = blockIdx.y;
    const int b  = blockIdx.z;
    const int t0 = qt * 128;

    // group 1: Q tile (hi only)
#pragma unroll
    for (int i = 0; i < 4; i++) {
        int idx = tid + i * 256;
        int row = idx >> 3;
        int seg = idx & 7;
        size_t go = (size_t)(b * NCTX + t0 + row) * WIDTH + h * ACH + seg * 8;
        cp16(sb + AQH + (uint32_t)(row * APITCH + seg * 16), g_qh + go);
    }
    cp_commit();
    load_kv_stage(sb + AST, b, h, 0, tid);
    cp_commit();
    load_kv_stage(sb + AST + ASTAGE, b, h, 64, tid);
    cp_commit();

    asm volatile("cp.async.wait_group 2;" ::: "memory");
    __syncthreads();
    uint32_t qhf[4][4];
    {
        uint32_t qa = (uint32_t)((wid * 16 + (lane & 15)) * APITCH + ((lane >> 4) << 4));
#pragma unroll
        for (int kc = 0; kc < 4; kc++)
            LDMATRIX_X4(qhf[kc], sb + AQH + qa + kc * 32);
    }

    const uint32_t kb = (uint32_t)(((lane & 7) + ((lane >> 4) << 3)) * APITCH
                                   + (((lane >> 3) & 1) << 4));
    const uint32_t vb = (uint32_t)((lane & 15) * APITCH + ((lane >> 4) << 4));

    float m2[2] = {-1e30f, -1e30f};
    float l[2]  = {0.0f, 0.0f};
    float o[8][4];
#pragma unroll
    for (int j = 0; j < 8; j++)
#pragma unroll
        for (int e = 0; e < 4; e++) o[j][e] = 0.0f;

    const float CS = 0.125f * 1.44269504f;

    const int NCHUNK = NDATA / 64;    // 64
    for (int sc = 0; sc < NCHUNK; sc++) {
        asm volatile("cp.async.wait_group 1;" ::: "memory");
        __syncthreads();

        if (sc + 2 < NCHUNK) {
            load_kv_stage(sb + AST + (uint32_t)((sc + 2) & 3) * ASTAGE,
                          b, h, (sc + 2) * 64, tid);
            cp_commit();
        }

        uint32_t st = sb + AST + (uint32_t)(sc & 3) * ASTAGE;

        // ---- S = Qh Kh^T (pure bf16) ----
        float sacc[8][4];
#pragma unroll
        for (int j = 0; j < 8; j++)
#pragma unroll
            for (int e = 0; e < 4; e++) sacc[j][e] = 0.0f;

#pragma unroll
        for (int kc = 0; kc < 4; kc++) {
#pragma unroll
            for (int g = 0; g < 4; g++) {
                uint32_t khf[4];
                LDMATRIX_X4(khf, st + TKH + kb + (uint32_t)(g * 16 * APITCH) + kc * 32);
                MMA16816(sacc[2 * g],     qhf[kc], khf[0], khf[1]);
                MMA16816(sacc[2 * g + 1], qhf[kc], khf[2], khf[3]);
            }
        }

        // ---- online softmax (base-2, scale folded) ----
        float mx0 = -1e30f, mx1 = -1e30f;
#pragma unroll
        for (int j = 0; j < 8; j++) {
            mx0 = fmaxf(mx0, fmaxf(sacc[j][0], sacc[j][1]));
            mx1 = fmaxf(mx1, fmaxf(sacc[j][2], sacc[j][3]));
        }
        mx0 *= CS; mx1 *= CS;
        mx0 = fmaxf(mx0, __shfl_xor_sync(0xffffffffu, mx0, 1));
        mx0 = fmaxf(mx0, __shfl_xor_sync(0xffffffffu, mx0, 2));
        mx1 = fmaxf(mx1, __shfl_xor_sync(0xffffffffu, mx1, 1));
        mx1 = fmaxf(mx1, __shfl_xor_sync(0xffffffffu, mx1, 2));
        float mn0 = fmaxf(m2[0], mx0), mn1 = fmaxf(m2[1], mx1);
        float c0 = exp2f(m2[0] - mn0), c1 = exp2f(m2[1] - mn1);
        m2[0] = mn0; m2[1] = mn1;

        float rs0 = 0.0f, rs1 = 0.0f;
#pragma unroll
        for (int j = 0; j < 8; j++) {
            float p0 = exp2f(fmaf(sacc[j][0], CS, -mn0));
            float p1 = exp2f(fmaf(sacc[j][1], CS, -mn0));
            float p2 = exp2f(fmaf(sacc[j][2], CS, -mn1));
            float p3 = exp2f(fmaf(sacc[j][3], CS, -mn1));
            sacc[j][0] = p0; sacc[j][1] = p1; sacc[j][2] = p2; sacc[j][3] = p3;
            rs0 += p0 + p1; rs1 += p2 + p3;
        }
        rs0 += __shfl_xor_sync(0xffffffffu, rs0, 1);
        rs0 += __shfl_xor_sync(0xffffffffu, rs0, 2);
        rs1 += __shfl_xor_sync(0xffffffffu, rs1, 1);
        rs1 += __shfl_xor_sync(0xffffffffu, rs1, 2);
        l[0] = l[0] * c0 + rs0;
        l[1] = l[1] * c1 + rs1;
#pragma unroll
        for (int j = 0; j < 8; j++) {
            o[j][0] *= c0; o[j][1] *= c0;
            o[j][2] *= c1; o[j][3] *= c1;
        }

        // ---- pack P into A fragments (hi + residual) ----
        uint32_t ph[4][4], pl[4][4];
#pragma unroll
        for (int kc = 0; kc < 4; kc++) {
            int j0 = 2 * kc, j1 = 2 * kc + 1;
            split2(sacc[j0][0], sacc[j0][1], ph[kc][0], pl[kc][0]);
            split2(sacc[j0][2], sacc[j0][3], ph[kc][1], pl[kc][1]);
            split2(sacc[j1][0], sacc[j1][1], ph[kc][2], pl[kc][2]);
            split2(sacc[j1][2], sacc[j1][3], ph[kc][3], pl[kc][3]);
        }

        // ---- O += P V (bf16x3) ----
#pragma unroll
        for (int kc = 0; kc < 4; kc++) {
#pragma unroll
            for (int g = 0; g < 4; g++) {
                uint32_t vo = vb + (uint32_t)(kc * 16 * APITCH) + g * 32;
                uint32_t vhf[4], vlf[4];
                LDMATRIX_X4T(vhf, st + TVH + vo);
                LDMATRIX_X4T(vlf, st + TVL + vo);
                MMA16816(o[2 * g],     ph[kc], vhf[0], vhf[1]);
                MMA16816(o[2 * g + 1], ph[kc], vhf[2], vhf[3]);
                MMA16816(o[2 * g],     ph[kc], vlf[0], vlf[1]);
                MMA16816(o[2 * g + 1], ph[kc], vlf[2], vlf[3]);
                MMA16816(o[2 * g],     pl[kc], vhf[0], vhf[1]);
                MMA16816(o[2 * g + 1], pl[kc], vhf[2], vhf[3]);
            }
        }
    }

    // ---- epilogue: normalize, split, store ----
    float inv0 = 1.0f / l[0];
    float inv1 = 1.0f / l[1];
    int r = t0 + wid * 16 + (lane >> 2);
    int cq = (lane & 3) * 2;
#pragma unroll
    for (int j = 0; j < 8; j++) {
        int col = h * ACH + j * 8 + cq;
        uint32_t hv, lv;
        split2(o[j][0] * inv0, o[j][1] * inv0, hv, lv);
        *(uint32_t*)&g_ah[(size_t)(b * NCTX + r) * WIDTH + col] = hv;
        *(uint32_t*)&g_al[(size_t)(b * NCTX + r) * WIDTH + col] = lv;
        split2(o[j][2] * inv1, o[j][3] * inv1, hv, lv);
        *(uint32_t*)&g_ah[(size_t)(b * NCTX + r + 8) * WIDTH + col] = hv;
        *(uint32_t*)&g_al[(size_t)(b * NCTX + r + 8) * WIDTH + col] = lv;
    }
}

// ---------------- launch ------------------------------------------------------
extern "C" void kernel_launch(void* const* d_in, const int* in_sizes, int n_in,
                              void* d_out, int out_size)
{
    (void)in_sizes; (void)n_in; (void)out_size;

    const float* x     = (const float*)d_in[0];
    const float* data  = (const float*)d_in[1];
    const float* Wq    = (const float*)d_in[2];
    const float* bq    = (const float*)d_in[3];
    const float* Wkv   = (const float*)d_in[4];
    const float* bkv   = (const float*)d_in[5];
    const float* Wproj = (const float*)d_in[6];
    const float* bproj = (const float*)d_in[7];
    float* out = (float*)d_out;

    __nv_bfloat16 *xh, *xl, *dh, *dl, *wqh, *wql, *wkvh, *wkvl, *wph, *wpl;
    __nv_bfloat16 *qh, *ql, *kvh, *kvl, *ah, *al;
    cudaGetSymbolAddress((void**)&xh,  g_xh);  cudaGetSymbolAddress((void**)&xl,  g_xl);
    cudaGetSymbolAddress((void**)&dh,  g_dh);  cudaGetSymbolAddress((void**)&dl,  g_dl);
    cudaGetSymbolAddress((void**)&wqh, g_wqh); cudaGetSymbolAddress((void**)&wql, g_wql);
    cudaGetSymbolAddress((void**)&wkvh,g_wkvh);cudaGetSymbolAddress((void**)&wkvl,g_wkvl);
    cudaGetSymbolAddress((void**)&wph, g_wph); cudaGetSymbolAddress((void**)&wpl, g_wpl);
    cudaGetSymbolAddress((void**)&qh,  g_qh);  cudaGetSymbolAddress((void**)&ql,  g_ql);
    cudaGetSymbolAddress((void**)&kvh, g_kvh); cudaGetSymbolAddress((void**)&kvl, g_kvl);
    cudaGetSymbolAddress((void**)&ah,  g_ah);  cudaGetSymbolAddress((void**)&al,  g_al);

    cudaFuncSetAttribute(gemm_bf16x3_kernel,
                         cudaFuncAttributeMaxDynamicSharedMemorySize, GEMM_SMEM);
    cudaFuncSetAttribute(attn_hmma_kernel,
                         cudaFuncAttributeMaxDynamicSharedMemorySize, ATTN_SMEM);

    // 1. input splits & weight transposes
    split_kernel<<<(MQ * WIDTH) / 256, 256>>>(x, xh, xl, MQ * WIDTH);
    split_kernel<<<(MKV * WIDTH) / 256, 256>>>(data, dh, dl, MKV * WIDTH);
    {
        dim3 blk(32, 8);
        transpose_split_kernel<<<dim3(WIDTH / 32, WIDTH / 32), blk>>>(Wq, wqh, wql, WIDTH, WIDTH);
        transpose_split_kernel<<<dim3(NKV / 32, WIDTH / 32), blk>>>(Wkv, wkvh, wkvl, WIDTH, NKV);
        transpose_split_kernel<<<dim3(WIDTH / 32, WIDTH / 32), blk>>>(Wproj, wph, wpl, WIDTH, WIDTH);
    }

    // 2. q = x @ Wq + bq  -> bf16 hi only (attention uses pure-bf16 QK^T)
    gemm_bf16x3_kernel<<<dim3(WIDTH / 128, MQ / 128), 256, GEMM_SMEM>>>(
        xh, xl, wqh, wql, bq, nullptr, qh, ql, MQ, WIDTH, WIDTH, 2);

    // 3. kv = data @ Wkv + bkv -> K half: hi only; V half: hi+lo
    gemm_bf16x3_kernel<<<dim3(NKV / 128, MKV / 128), 256, GEMM_SMEM>>>(
        dh, dl, wkvh, wkvl, bkv, nullptr, kvh, kvl, MKV, NKV, WIDTH, 3);

    // 4. attention -> split bf16 output
    attn_hmma_kernel<<<dim3(NCTX / 128, HEADS, BS), 256, ATTN_SMEM>>>();

    // 5. out = attn @ Wproj + bproj  (fp32 output)
    gemm_bf16x3_kernel<<<dim3(WIDTH / 128, MQ / 128), 256, GEMM_SMEM>>>(
        ah, al, wph, wpl, bproj, out, nullptr, nullptr, MQ, WIDTH, WIDTH, 0);
}